// round 13
// baseline (speedup 1.0000x reference)
#include <cuda_runtime.h>
#include <math.h>

// ---------------- problem constants ----------------
constexpr int Dd   = 512;
constexpr int Hn   = 8;
constexpr int DFFd = 2048;
constexpr int KWn  = 31;
constexpr int Ln   = 2;
constexpr int Bn   = 4;
constexpr int Tn   = 1024;
constexpr int DKn  = 64;
constexpr int Pn   = 2 * Tn - 1;      // 2047
constexpr int BTn  = Bn * Tn;         // 4096
constexpr float EPSf   = 1e-5f;
constexpr float SCALEf = 0.125f;      // 1/sqrt(64)

// rounded-weight scratch layout (floats)
constexpr size_t OFF_FF1W1 = 0;
constexpr size_t OFF_FF1W2 = OFF_FF1W1 + (size_t)Ln * Dd * DFFd;
constexpr size_t OFF_FF2W1 = OFF_FF1W2 + (size_t)Ln * DFFd * Dd;
constexpr size_t OFF_FF2W2 = OFF_FF2W1 + (size_t)Ln * Dd * DFFd;
constexpr size_t OFF_WQKV  = OFF_FF2W2 + (size_t)Ln * DFFd * Dd;   // [Ln][512][1536]
constexpr size_t OFF_WO    = OFF_WQKV + (size_t)Ln * Dd * 3 * Dd;
constexpr size_t OFF_WP    = OFF_WO + (size_t)Ln * Dd * Dd;
constexpr size_t OFF_PW1   = OFF_WP + (size_t)Ln * Dd * Dd;
constexpr size_t OFF_PW2   = OFF_PW1 + (size_t)Ln * Dd * 2 * Dd;
constexpr size_t OFF_BQKV  = OFF_PW2 + (size_t)Ln * Dd * Dd;       // [Ln][1536]
constexpr size_t WR_TOTAL  = OFF_BQKV + (size_t)Ln * 3 * Dd;

// GEMM dynamic smem: 3 stages x (A 128x32 + B 32xBN) u32
constexpr int GEMM_SMEM_64  = 3 * (128 * 32 + 32 * 64) * 4;    // 73728 B
constexpr int GEMM_SMEM_128 = 3 * (128 * 32 + 32 * 128) * 4;   // 98304 B

// ---------------- device scratch (allocation-free) ----------------
__device__ float g_X  [BTn * Dd];
__device__ float g_H  [BTn * Dd];
__device__ float g_FF [BTn * DFFd];
__device__ float g_QKV[(size_t)BTn * 3 * Dd];
__device__ float g_P  [Pn * Dd];
__device__ float g_PosR[Pn * Dd];          // tf32-rounded pos (dedicated)
__device__ float g_S  [(size_t)Bn * Hn * Tn * Tn];  // 128 MB scores
__device__ float g_CTX[BTn * Dd];
__device__ float g_Y2 [BTn * 2 * Dd];
__device__ float g_CV [Bn * Dd * Tn];
__device__ float g_CV2[Bn * Dd * Tn];
__device__ float g_mu [Dd];
__device__ float g_rstd[Dd];
__device__ float g_WR [WR_TOTAL];          // tf32-rounded weights

__device__ __forceinline__ float sigf(float x) { return 1.0f / (1.0f + expf(-x)); }

__device__ __forceinline__ unsigned f2tf32(float x) {
    unsigned u;
    asm("cvt.rna.tf32.f32 %0, %1;" : "=r"(u) : "f"(x));
    return u;
}
__device__ __forceinline__ float rnd_tf32(float x) { return __uint_as_float(f2tf32(x)); }

#define MMA_TF32(c0,c1,c2,c3,a0,a1,a2,a3,b0,b1)                              \
    asm volatile(                                                            \
        "mma.sync.aligned.m16n8k8.row.col.f32.tf32.tf32.f32 "                \
        "{%0,%1,%2,%3},{%4,%5,%6,%7},{%8,%9},{%0,%1,%2,%3};"                 \
        : "+f"(c0), "+f"(c1), "+f"(c2), "+f"(c3)                             \
        : "r"(a0), "r"(a1), "r"(a2), "r"(a3), "r"(b0), "r"(b1))

__device__ __forceinline__ void cpa16(unsigned dst, const void* src, int szbytes) {
    asm volatile("cp.async.cg.shared.global [%0], [%1], 16, %2;"
                 :: "r"(dst), "l"(src), "r"(szbytes));
}

// =======================================================================
// TF32 tensor-core GEMM, cp.async 3-stage pipeline, XOR-swizzled dyn smem.
// C = epilogue(A (MxK, lda) @ W (KxN, ldw) + bias)
// Tile: BM=128, BN = 64 or 128 (template), BK=32. 256 threads = 8 warps
// (4x2); warp tile 32 x BN/2 via 2 x (BN/16) m16n8k8 fragments.
// Inputs MUST be tf32-pre-rounded floats.
// MODE: 0 = (+bias, rnd), 1 = silu(+bias, rnd), 2 = res + (.), 3 = res + 0.5*(.)
// AV: blockIdx.z decodes (b,h) for the attn-prob @ V batched GEMM.
// =======================================================================
template <int MODE, bool AV, int BNt>
__global__ void __launch_bounds__(256, 2) tf32gemm(
    const float* __restrict__ A, int lda,
    const float* __restrict__ W, int ldw,
    const float* __restrict__ bias,
    const float* __restrict__ res,
    float* __restrict__ C, int ldc,
    int M, int N, int Kd)
{
    constexpr int CHUNKS = BNt / 4;                 // B 16B-chunks per k-row
    constexpr int STAGE_U32 = 128 * 32 + 32 * BNt;
    constexpr int NT = BNt / 16;                    // n fragments per warp
    extern __shared__ unsigned gsm[];

    if (AV) {
        int z = blockIdx.z;                       // z = b*8 + h
        A += (size_t)z * Tn * Tn;                 // S[b][h] (T x T)
        W += (size_t)(z >> 3) * Tn * ldw + (size_t)(z & 7) * DKn;
        C += (size_t)(z >> 3) * Tn * ldc + (size_t)(z & 7) * DKn;
    }

    const int bm = blockIdx.y * 128, bn = blockIdx.x * BNt;
    const int tid  = threadIdx.x;
    const int warp = tid >> 5, lane = tid & 31;
    const int g = lane >> 2, t = lane & 3;
    const int wm = (warp >> 1) * 32, wn = (warp & 1) * (BNt / 2);

    unsigned smBase = (unsigned)__cvta_generic_to_shared(gsm);

    auto loadTile = [&](int stage, int k0) {
        unsigned aOff = (unsigned)stage * STAGE_U32;
#pragma unroll
        for (int i = 0; i < 4; i++) {
            int lin = i * 256 + tid;
            int row = lin >> 3, ck = lin & 7;
            int pc = ck ^ (row & 7);
            unsigned dst = smBase + (aOff + row * 32 + pc * 4) * 4;
            const float* src = A + (size_t)(bm + row) * lda + k0 + ck * 4;
            cpa16(dst, src, (bm + row < M) ? 16 : 0);
        }
        unsigned bOff = aOff + 4096;
#pragma unroll
        for (int i = 0; i < CHUNKS / 8; i++) {
            int lin = i * 256 + tid;
            int kr = lin / CHUNKS, c4 = lin % CHUNKS;
            int pc = c4 ^ (2 * (kr & 3));
            unsigned dst = smBase + (bOff + kr * BNt + pc * 4) * 4;
            const float* src = W + (size_t)(k0 + kr) * ldw + bn + c4 * 4;
            cpa16(dst, src, 16);
        }
        asm volatile("cp.async.commit_group;");
    };

    float acc[2][NT][4] = {};

    int colB[NT];
#pragma unroll
    for (int nt = 0; nt < NT; nt++) {
        int nb = wn + nt * 8 + g;
        colB[nt] = (((nb >> 2) ^ (2 * t)) << 2) | (nb & 3);
    }
    const int rA0 = wm + g, rA1 = wm + 16 + g;

    const int nk = Kd >> 5;
    loadTile(0, 0);
    loadTile(1, 32);

    for (int kb = 0; kb < nk; kb++) {
        if (kb + 2 < nk) {
            asm volatile("cp.async.wait_group 1;");
        } else {
            asm volatile("cp.async.wait_group 0;");
        }
        __syncthreads();

        const unsigned* Ac = gsm + (kb % 3) * STAGE_U32;
        const unsigned* Bc = Ac + 4096;
#pragma unroll
        for (int kt = 0; kt < 4; kt++) {
            const int c0 = (((2 * kt) ^ g) << 2) | t;
            const int c1 = (((2 * kt + 1) ^ g) << 2) | t;
            const int kr = kt * 8 + t;
            unsigned a[2][4];
            a[0][0] = Ac[rA0 * 32 + c0];       a[0][1] = Ac[(rA0 + 8) * 32 + c0];
            a[0][2] = Ac[rA0 * 32 + c1];       a[0][3] = Ac[(rA0 + 8) * 32 + c1];
            a[1][0] = Ac[rA1 * 32 + c0];       a[1][1] = Ac[(rA1 + 8) * 32 + c0];
            a[1][2] = Ac[rA1 * 32 + c1];       a[1][3] = Ac[(rA1 + 8) * 32 + c1];
            unsigned b[NT][2];
#pragma unroll
            for (int nt = 0; nt < NT; nt++) {
                b[nt][0] = Bc[kr * BNt + colB[nt]];
                b[nt][1] = Bc[(kr + 4) * BNt + colB[nt]];
            }
#pragma unroll
            for (int mt = 0; mt < 2; mt++)
#pragma unroll
                for (int nt = 0; nt < NT; nt++)
                    MMA_TF32(acc[mt][nt][0], acc[mt][nt][1], acc[mt][nt][2], acc[mt][nt][3],
                             a[mt][0], a[mt][1], a[mt][2], a[mt][3],
                             b[nt][0], b[nt][1]);
        }
        if (kb + 2 < nk) loadTile((kb + 2) % 3, (kb + 2) * 32);
    }

#pragma unroll
    for (int mt = 0; mt < 2; mt++) {
        int r0 = bm + wm + mt * 16 + g;
        int r1 = r0 + 8;
#pragma unroll
        for (int nt = 0; nt < NT; nt++) {
            int col = bn + wn + nt * 8 + 2 * t;
#pragma unroll
            for (int half = 0; half < 2; half++) {
                int row = half ? r1 : r0;
                if (row >= M) continue;
                float v0 = acc[mt][nt][half * 2 + 0];
                float v1 = acc[mt][nt][half * 2 + 1];
                if (bias) { v0 += bias[col]; v1 += bias[col + 1]; }
                if (MODE == 1) { v0 = v0 * sigf(v0); v1 = v1 * sigf(v1); }
                if (MODE == 0 || MODE == 1) { v0 = rnd_tf32(v0); v1 = rnd_tf32(v1); }
                if (MODE == 2) {
                    v0 = res[(size_t)row * ldc + col] + v0;
                    v1 = res[(size_t)row * ldc + col + 1] + v1;
                }
                if (MODE == 3) {
                    v0 = res[(size_t)row * ldc + col] + 0.5f * v0;
                    v1 = res[(size_t)row * ldc + col + 1] + 0.5f * v1;
                }
                *(float2*)&C[(size_t)row * ldc + col] = make_float2(v0, v1);
            }
        }
    }
}

// ---------------- LayerNorm: 128 threads, float4, warp shuffles ----------------
template <bool RND>
__global__ void __launch_bounds__(128) ln_kernel(
    const float* __restrict__ x, const float* __restrict__ s,
    const float* __restrict__ b, float* __restrict__ out)
{
    __shared__ float red[8];
    const int row = blockIdx.x;
    const int tid = threadIdx.x;
    const int lane = tid & 31, wid = tid >> 5;
    float4 v = ((const float4*)(x + (size_t)row * Dd))[tid];

    float s1 = v.x + v.y + v.z + v.w;
#pragma unroll
    for (int o = 16; o > 0; o >>= 1) s1 += __shfl_xor_sync(0xffffffffu, s1, o);
    if (lane == 0) red[wid] = s1;
    __syncthreads();
    float mean = (red[0] + red[1] + red[2] + red[3]) * (1.0f / Dd);

    float4 d;
    d.x = v.x - mean; d.y = v.y - mean; d.z = v.z - mean; d.w = v.w - mean;
    float s2 = d.x * d.x + d.y * d.y + d.z * d.z + d.w * d.w;
#pragma unroll
    for (int o = 16; o > 0; o >>= 1) s2 += __shfl_xor_sync(0xffffffffu, s2, o);
    if (lane == 0) red[4 + wid] = s2;
    __syncthreads();
    float rstd = rsqrtf((red[4] + red[5] + red[6] + red[7]) * (1.0f / Dd) + EPSf);

    float4 sc = ((const float4*)s)[tid];
    float4 bc = ((const float4*)b)[tid];
    float4 o4;
    o4.x = d.x * rstd * sc.x + bc.x;
    o4.y = d.y * rstd * sc.y + bc.y;
    o4.z = d.z * rstd * sc.z + bc.z;
    o4.w = d.w * rstd * sc.w + bc.w;
    if (RND) {
        o4.x = rnd_tf32(o4.x); o4.y = rnd_tf32(o4.y);
        o4.z = rnd_tf32(o4.z); o4.w = rnd_tf32(o4.w);
    }
    ((float4*)(out + (size_t)row * Dd))[tid] = o4;
}

// =======================================================================
// rel-pos attention scores on tensor cores (R8-verified).
// S[b,h,t,s] = ((q+u)·k[s] + (q+v)·p[T-1-t+s]) * SCALE
// =======================================================================
__global__ void __launch_bounds__(256) attn_scores(
    const float* __restrict__ Q, int ldq,
    const float* __restrict__ Km, int ldk,
    const float* __restrict__ Pm,
    const float* __restrict__ bu, const float* __restrict__ bvv,
    float* __restrict__ S)
{
    __shared__ unsigned qs[32][66], kt[32][66], pw[64][66];
    __shared__ float C1[32][33];
    __shared__ float C2[32][68];
    __shared__ float uk[32], vp[64];
    __shared__ float us[64], vs[64];

    const int z = blockIdx.z;
    const int b = z >> 3, h = z & 7;
    const int t0 = blockIdx.y << 5, s0 = blockIdx.x << 5;
    const int tid = threadIdx.x;

    if (tid < 16)
        ((float4*)us)[tid] = ((const float4*)(bu + h * 64))[tid];
    else if (tid < 32)
        ((float4*)vs)[tid - 16] = ((const float4*)(bvv + h * 64))[tid - 16];

    for (int i = tid; i < 512; i += 256) {
        int r = i >> 4, c = (i & 15) * 4;
        float4 q4 = *(const float4*)&Q[(size_t)(b * Tn + t0 + r) * ldq + h * 64 + c];
        qs[r][c + 0] = f2tf32(q4.x);
        qs[r][c + 1] = f2tf32(q4.y);
        qs[r][c + 2] = f2tf32(q4.z);
        qs[r][c + 3] = f2tf32(q4.w);
        float4 k4 = *(const float4*)&Km[(size_t)(b * Tn + s0 + r) * ldk + h * 64 + c];
        kt[r][c + 0] = f2tf32(k4.x);
        kt[r][c + 1] = f2tf32(k4.y);
        kt[r][c + 2] = f2tf32(k4.z);
        kt[r][c + 3] = f2tf32(k4.w);
    }
    const int base = (Tn - 32) - t0 + s0;     // in [0, P-63]
    for (int i = tid; i < 1024; i += 256) {
        int r = i >> 4, c = (i & 15) * 4;
        if (r < 63) {
            float4 p4 = *(const float4*)&Pm[(size_t)(base + r) * Dd + h * 64 + c];
            pw[r][c + 0] = f2tf32(p4.x);
            pw[r][c + 1] = f2tf32(p4.y);
            pw[r][c + 2] = f2tf32(p4.z);
            pw[r][c + 3] = f2tf32(p4.w);
        } else {
            pw[r][c + 0] = 0u; pw[r][c + 1] = 0u; pw[r][c + 2] = 0u; pw[r][c + 3] = 0u;
        }
    }
    __syncthreads();

    const int warp = tid >> 5, lane = tid & 31;
    const int g = lane >> 2, t = lane & 3;
    const int mw  = (warp >> 2) * 16;
    const int nwA = (warp & 3) * 8;
    const int nw2 = (warp & 3) * 16;

    float c1r[4] = {};
    float e[2][4] = {};
#pragma unroll
    for (int k0 = 0; k0 < 64; k0 += 8) {
        const int k = k0 + t;
        unsigned a0 = qs[mw + g][k],     a1 = qs[mw + 8 + g][k];
        unsigned a2 = qs[mw + g][k + 4], a3 = qs[mw + 8 + g][k + 4];
        unsigned b0 = kt[nwA + g][k],    b1 = kt[nwA + g][k + 4];
        MMA_TF32(c1r[0], c1r[1], c1r[2], c1r[3], a0, a1, a2, a3, b0, b1);
#pragma unroll
        for (int nt = 0; nt < 2; nt++) {
            int nb = nw2 + nt * 8 + g;
            unsigned p0 = pw[nb][k], p1 = pw[nb][k + 4];
            MMA_TF32(e[nt][0], e[nt][1], e[nt][2], e[nt][3], a0, a1, a2, a3, p0, p1);
        }
    }
    C1[mw + g][nwA + 2 * t]         = c1r[0];
    C1[mw + g][nwA + 2 * t + 1]     = c1r[1];
    C1[mw + 8 + g][nwA + 2 * t]     = c1r[2];
    C1[mw + 8 + g][nwA + 2 * t + 1] = c1r[3];
#pragma unroll
    for (int nt = 0; nt < 2; nt++) {
        int nb = nw2 + nt * 8;
        C2[mw + g][nb + 2 * t]         = e[nt][0];
        C2[mw + g][nb + 2 * t + 1]     = e[nt][1];
        C2[mw + 8 + g][nb + 2 * t]     = e[nt][2];
        C2[mw + 8 + g][nb + 2 * t + 1] = e[nt][3];
    }

    if (tid < 32) {
        float s = 0.f;
#pragma unroll 8
        for (int d = 0; d < 64; d++) s += us[d] * __uint_as_float(kt[tid][d]);
        uk[tid] = s;
    } else if (tid < 96) {
        int r = tid - 32;
        float s = 0.f;
#pragma unroll 8
        for (int d = 0; d < 64; d++) s += vs[d] * __uint_as_float(pw[r][d]);
        vp[r] = s;
    }
    __syncthreads();

    const int tl = tid >> 3, sl = (tid & 7) * 4;
    const int pr = 31 - tl + sl;
    float4 o4;
    o4.x = (C1[tl][sl + 0] + uk[sl + 0] + C2[tl][pr + 0] + vp[pr + 0]) * SCALEf;
    o4.y = (C1[tl][sl + 1] + uk[sl + 1] + C2[tl][pr + 1] + vp[pr + 1]) * SCALEf;
    o4.z = (C1[tl][sl + 2] + uk[sl + 2] + C2[tl][pr + 2] + vp[pr + 2]) * SCALEf;
    o4.w = (C1[tl][sl + 3] + uk[sl + 3] + C2[tl][pr + 3] + vp[pr + 3]) * SCALEf;
    *(float4*)&S[((size_t)z * Tn + (t0 + tl)) * Tn + (s0 + sl)] = o4;
}

// ---------------- row softmax over T=1024 (tf32-rounded output) ----------------
__global__ void __launch_bounds__(256) softmax_kernel(float* __restrict__ S)
{
    __shared__ float red[256];
    float4* p = (float4*)(S + (size_t)blockIdx.x * Tn);
    const int tid = threadIdx.x;
    float4 x = p[tid];
    float m = fmaxf(fmaxf(x.x, x.y), fmaxf(x.z, x.w));
    red[tid] = m;
    __syncthreads();
    for (int o = 128; o > 0; o >>= 1) {
        if (tid < o) red[tid] = fmaxf(red[tid], red[tid + o]);
        __syncthreads();
    }
    m = red[0];
    __syncthreads();
    x.x = expf(x.x - m); x.y = expf(x.y - m); x.z = expf(x.z - m); x.w = expf(x.w - m);
    red[tid] = x.x + x.y + x.z + x.w;
    __syncthreads();
    for (int o = 128; o > 0; o >>= 1) {
        if (tid < o) red[tid] += red[tid + o];
        __syncthreads();
    }
    float inv = 1.0f / red[0];
    x.x = rnd_tf32(x.x * inv); x.y = rnd_tf32(x.y * inv);
    x.z = rnd_tf32(x.z * inv); x.w = rnd_tf32(x.w * inv);
    p[tid] = x;
}

// ---------------- GLU + transpose (B,T,2D) -> (B,D,T), tiled ----------------
__global__ void __launch_bounds__(256) glu_tr(const float* __restrict__ Y2,
                                              float* __restrict__ CV)
{
    __shared__ float tile[32][33];
    const int b = blockIdx.z;
    const int d0 = blockIdx.y * 32, t0 = blockIdx.x * 32;
    const int tid = threadIdx.x;
    const int rr = tid >> 5, cc = tid & 31;
#pragma unroll
    for (int i = 0; i < 4; i++) {
        int tl = rr + i * 8;
        size_t base = (size_t)(b * Tn + t0 + tl) * (2 * Dd) + d0 + cc;
        float a = Y2[base];
        float g = Y2[base + Dd];
        tile[tl][cc] = a * sigf(g);
    }
    __syncthreads();
#pragma unroll
    for (int i = 0; i < 4; i++) {
        int dl = rr + i * 8;
        CV[((size_t)b * Dd + d0 + dl) * Tn + t0 + cc] = tile[cc][dl];
    }
}

// ---------------- depthwise conv K=31, pad 15 ----------------
__global__ void __launch_bounds__(128) dwconv_kernel(
    const float* __restrict__ CV, const float* __restrict__ w,
    const float* __restrict__ bias, float* __restrict__ out)
{
    __shared__ float sin_[128 + 30];
    __shared__ float sw[31];
    const int t0 = blockIdx.x * 128;
    const int d = blockIdx.y;
    const int b = blockIdx.z;
    const float* ip = CV + ((size_t)b * Dd + d) * Tn;
    const int tid = threadIdx.x;
    for (int i = tid; i < 158; i += 128) {
        int t = t0 - 15 + i;
        sin_[i] = (t >= 0 && t < Tn) ? ip[t] : 0.0f;
    }
    if (tid < 31) sw[tid] = w[d * KWn + tid];
    __syncthreads();
    float acc = bias[d];
#pragma unroll
    for (int k = 0; k < 31; k++) acc += sin_[tid + k] * sw[k];
    out[((size_t)b * Dd + d) * Tn + t0 + tid] = acc;
}

// ---------------- BatchNorm stats ----------------
__global__ void __launch_bounds__(256) bn_stats(const float* __restrict__ y)
{
    __shared__ float rs[256], rs2[256];
    const int d = blockIdx.x;
    const int tid = threadIdx.x;
    float s = 0.f, s2 = 0.f;
    for (int b = 0; b < Bn; b++) {
        const float* p = y + ((size_t)b * Dd + d) * Tn;
        for (int t = tid; t < Tn; t += 256) {
            float v = p[t];
            s += v;
            s2 += v * v;
        }
    }
    rs[tid] = s; rs2[tid] = s2;
    __syncthreads();
    for (int o = 128; o > 0; o >>= 1) {
        if (tid < o) { rs[tid] += rs[tid + o]; rs2[tid] += rs2[tid + o]; }
        __syncthreads();
    }
    if (tid == 0) {
        float mu = rs[0] * (1.0f / (Bn * Tn));
        float var = rs2[0] * (1.0f / (Bn * Tn)) - mu * mu;
        g_mu[d] = mu;
        g_rstd[d] = rsqrtf(var + EPSf);
    }
}

// ---------------- BN apply + SiLU + transpose -> (B,T,D), tf32-rounded ----------------
__global__ void __launch_bounds__(256) bn_tr(
    const float* __restrict__ y, const float* __restrict__ g,
    const float* __restrict__ bt, float* __restrict__ out)
{
    __shared__ float tile[32][33];
    const int b = blockIdx.z;
    const int d0 = blockIdx.y * 32, t0 = blockIdx.x * 32;
    const int tid = threadIdx.x;
    const int rr = tid >> 5, cc = tid & 31;
#pragma unroll
    for (int i = 0; i < 4; i++) {
        int dl = rr + i * 8;
        int d = d0 + dl;
        float v = y[((size_t)b * Dd + d) * Tn + t0 + cc];
        v = (v - g_mu[d]) * g_rstd[d] * g[d] + bt[d];
        v = v * sigf(v);
        tile[dl][cc] = rnd_tf32(v);
    }
    __syncthreads();
#pragma unroll
    for (int i = 0; i < 4; i++) {
        int tl = rr + i * 8;
        out[(size_t)(b * Tn + t0 + tl) * Dd + d0 + cc] = tile[cc][tl];
    }
}

// ---------------- copy ----------------
__global__ void __launch_bounds__(256) copy_kernel(const float* __restrict__ in,
                                                   float* __restrict__ out, int n)
{
    int i = blockIdx.x * 256 + threadIdx.x;
    if (i < n) out[i] = in[i];
}

// ---------------- consolidated tf32 rounding / packing prologue ----------------
constexpr int NSEG = 15;
struct RPack {
    const float* src[NSEG];
    float*       dst[NSEG];
    int n[NSEG];
    int cols[NSEG];
    int dstld[NSEG];
};
__global__ void __launch_bounds__(256) round_multi(RPack p)
{
    int sgi = blockIdx.y;
    int i = blockIdx.x * 256 + threadIdx.x;
    if (i >= p.n[sgi]) return;
    int r = i / p.cols[sgi], c = i - r * p.cols[sgi];
    p.dst[sgi][(size_t)r * p.dstld[sgi] + c] = rnd_tf32(p.src[sgi][i]);
}

// ---------------- host-side launch helper (BN=128 path) ----------------
static void launch_tf32(int mode,
                        const float* A, int lda,
                        const float* W, int ldw,
                        const float* bias, const float* res,
                        float* C, int ldc,
                        int M, int N, int Kd)
{
    dim3 g(N / 128, (M + 127) / 128, 1);
    switch (mode) {
        case 0: tf32gemm<0, false, 128><<<g, 256, GEMM_SMEM_128>>>(A, lda, W, ldw, bias, res, C, ldc, M, N, Kd); break;
        case 1: tf32gemm<1, false, 128><<<g, 256, GEMM_SMEM_128>>>(A, lda, W, ldw, bias, res, C, ldc, M, N, Kd); break;
        case 2: tf32gemm<2, false, 128><<<g, 256, GEMM_SMEM_128>>>(A, lda, W, ldw, bias, res, C, ldc, M, N, Kd); break;
        case 3: tf32gemm<3, false, 128><<<g, 256, GEMM_SMEM_128>>>(A, lda, W, ldw, bias, res, C, ldc, M, N, Kd); break;
    }
}

extern "C" void kernel_launch(void* const* d_in, const int* in_sizes, int n_in,
                              void* d_out, int out_size)
{
    const float* in_x   = (const float*)d_in[0];
    const float* pos    = (const float*)d_in[1];
    const float* ln_s   = (const float*)d_in[2];
    const float* ln_b   = (const float*)d_in[3];
    const float* ff1_w1 = (const float*)d_in[4];
    const float* ff1_b1 = (const float*)d_in[5];
    const float* ff1_w2 = (const float*)d_in[6];
    const float* ff1_b2 = (const float*)d_in[7];
    const float* ff2_w1 = (const float*)d_in[8];
    const float* ff2_b1 = (const float*)d_in[9];
    const float* ff2_w2 = (const float*)d_in[10];
    const float* ff2_b2 = (const float*)d_in[11];
    const float* wq     = (const float*)d_in[12];
    const float* bq     = (const float*)d_in[13];
    const float* wk     = (const float*)d_in[14];
    const float* bk     = (const float*)d_in[15];
    const float* wv     = (const float*)d_in[16];
    const float* bv     = (const float*)d_in[17];
    const float* wp     = (const float*)d_in[18];
    const float* wo     = (const float*)d_in[19];
    const float* bo     = (const float*)d_in[20];
    const float* bias_u = (const float*)d_in[21];
    const float* bias_v = (const float*)d_in[22];
    const float* pw1_w  = (const float*)d_in[23];
    const float* pw1_b  = (const float*)d_in[24];
    const float* dw_w   = (const float*)d_in[25];
    const float* dw_b   = (const float*)d_in[26];
    const float* bn_g   = (const float*)d_in[27];
    const float* bn_b   = (const float*)d_in[28];
    const float* pw2_w  = (const float*)d_in[29];
    const float* pw2_b  = (const float*)d_in[30];
    (void)in_sizes; (void)n_in; (void)out_size;

    float *X, *Hb, *FF, *QKV, *Pb, *PosR, *Sb, *CTX, *Y2, *CV, *CV2, *WR;
    cudaGetSymbolAddress((void**)&X,    g_X);
    cudaGetSymbolAddress((void**)&Hb,   g_H);
    cudaGetSymbolAddress((void**)&FF,   g_FF);
    cudaGetSymbolAddress((void**)&QKV,  g_QKV);
    cudaGetSymbolAddress((void**)&Pb,   g_P);
    cudaGetSymbolAddress((void**)&PosR, g_PosR);
    cudaGetSymbolAddress((void**)&Sb,   g_S);
    cudaGetSymbolAddress((void**)&CTX,  g_CTX);
    cudaGetSymbolAddress((void**)&Y2,   g_Y2);
    cudaGetSymbolAddress((void**)&CV,   g_CV);
    cudaGetSymbolAddress((void**)&CV2,  g_CV2);
    cudaGetSymbolAddress((void**)&WR,   g_WR);

    cudaFuncSetAttribute((const void*)tf32gemm<0, false, 128>, cudaFuncAttributeMaxDynamicSharedMemorySize, GEMM_SMEM_128);
    cudaFuncSetAttribute((const void*)tf32gemm<1, false, 128>, cudaFuncAttributeMaxDynamicSharedMemorySize, GEMM_SMEM_128);
    cudaFuncSetAttribute((const void*)tf32gemm<2, false, 128>, cudaFuncAttributeMaxDynamicSharedMemorySize, GEMM_SMEM_128);
    cudaFuncSetAttribute((const void*)tf32gemm<3, false, 128>, cudaFuncAttributeMaxDynamicSharedMemorySize, GEMM_SMEM_128);
    cudaFuncSetAttribute((const void*)tf32gemm<0, true, 64>,   cudaFuncAttributeMaxDynamicSharedMemorySize, GEMM_SMEM_64);

    // consolidated tf32 rounding + QKV weight/bias interleave
    {
        RPack p;
        int i = 0;
        auto seg = [&](const float* s, float* d, size_t n, int cols, int ld) {
            p.src[i] = s; p.dst[i] = d; p.n[i] = (int)n; p.cols[i] = cols; p.dstld[i] = ld; i++;
        };
        seg(ff1_w1, WR + OFF_FF1W1, (size_t)Ln * Dd * DFFd, (int)((size_t)Ln * Dd * DFFd), (int)((size_t)Ln * Dd * DFFd));
        seg(ff1_w2, WR + OFF_FF1W2, (size_t)Ln * DFFd * Dd, (int)((size_t)Ln * DFFd * Dd), (int)((size_t)Ln * DFFd * Dd));
        seg(ff2_w1, WR + OFF_FF2W1, (size_t)Ln * Dd * DFFd, (int)((size_t)Ln * Dd * DFFd), (int)((size_t)Ln * Dd * DFFd));
        seg(ff2_w2, WR + OFF_FF2W2, (size_t)Ln * DFFd * Dd, (int)((size_t)Ln * DFFd * Dd), (int)((size_t)Ln * DFFd * Dd));
        seg(wo,     WR + OFF_WO,    (size_t)Ln * Dd * Dd, (int)((size_t)Ln * Dd * Dd), (int)((size_t)Ln * Dd * Dd));
        seg(wp,     WR + OFF_WP,    (size_t)Ln * Dd * Dd, (int)((size_t)Ln * Dd * Dd), (int)((size_t)Ln * Dd * Dd));
        seg(pw1_w,  WR + OFF_PW1,   (size_t)Ln * Dd * 2 * Dd, (int)((size_t)Ln * Dd * 2 * Dd), (int)((size_t)Ln * Dd * 2 * Dd));
        seg(pw2_w,  WR + OFF_PW2,   (size_t)Ln * Dd * Dd, (int)((size_t)Ln * Dd * Dd), (int)((size_t)Ln * Dd * Dd));
        seg(pos,    PosR,           (size_t)Pn * Dd, (int)((size_t)Pn * Dd), (int)((size_t)Pn * Dd));
        seg(wq, WR + OFF_WQKV + 0,        (size_t)Ln * Dd * Dd, Dd, 3 * Dd);
        seg(wk, WR + OFF_WQKV + Dd,       (size_t)Ln * Dd * Dd, Dd, 3 * Dd);
        seg(wv, WR + OFF_WQKV + 2 * Dd,   (size_t)Ln * Dd * Dd, Dd, 3 * Dd);
        seg(bq, WR + OFF_BQKV + 0,        (size_t)Ln * Dd, Dd, 3 * Dd);
        seg(bk, WR + OFF_BQKV + Dd,       (size_t)Ln * Dd, Dd, 3 * Dd);
        seg(bv, WR + OFF_BQKV + 2 * Dd,   (size_t)Ln * Dd, Dd, 3 * Dd);
        round_multi<<<dim3(((size_t)Ln * Dd * DFFd + 255) / 256, NSEG), 256>>>(p);
    }

    copy_kernel<<<(BTn * Dd) / 256, 256>>>(in_x, X, BTn * Dd);

    for (int l = 0; l < Ln; ++l) {
        const float* lnS = ln_s + (size_t)l * 5 * Dd;
        const float* lnB = ln_b + (size_t)l * 5 * Dd;

        // ---- macaron FFN 1 (half residual) ----
        ln_kernel<true><<<BTn, 128>>>(X, lnS, lnB, Hb);
        launch_tf32(1, Hb, Dd, WR + OFF_FF1W1 + (size_t)l * Dd * DFFd, DFFd,
                    ff1_b1 + (size_t)l * DFFd, nullptr, FF, DFFd, BTn, DFFd, Dd);
        launch_tf32(3, FF, DFFd, WR + OFF_FF1W2 + (size_t)l * DFFd * Dd, Dd,
                    ff1_b2 + (size_t)l * Dd, X, X, Dd, BTn, Dd, DFFd);

        // ---- rel-pos MHSA ----
        ln_kernel<true><<<BTn, 128>>>(X, lnS + Dd, lnB + Dd, Hb);
        launch_tf32(0, Hb, Dd, WR + OFF_WQKV + (size_t)l * Dd * 3 * Dd, 3 * Dd,
                    WR + OFF_BQKV + (size_t)l * 3 * Dd, nullptr, QKV, 3 * Dd, BTn, 3 * Dd, Dd);
        launch_tf32(0, PosR, Dd, WR + OFF_WP + (size_t)l * Dd * Dd, Dd,
                    nullptr, nullptr, Pb, Dd, Pn, Dd, Dd);

        attn_scores<<<dim3(Tn / 32, Tn / 32, Bn * Hn), 256>>>(
            QKV, 3 * Dd, QKV + Dd, 3 * Dd, Pb,
            bias_u + (size_t)l * Hn * DKn, bias_v + (size_t)l * Hn * DKn, Sb);
        softmax_kernel<<<Bn * Hn * Tn, 256>>>(Sb);

        tf32gemm<0, true, 64><<<dim3(1, Tn / 128, Bn * Hn), 256, GEMM_SMEM_64>>>(
            Sb, Tn, QKV + 2 * Dd, 3 * Dd, nullptr, nullptr, CTX, Dd, Tn, DKn, Tn);

        launch_tf32(2, CTX, Dd, WR + OFF_WO + (size_t)l * Dd * Dd, Dd,
                    bo + (size_t)l * Dd, X, X, Dd, BTn, Dd, Dd);

        // ---- conv module ----
        ln_kernel<true><<<BTn, 128>>>(X, lnS + 2 * Dd, lnB + 2 * Dd, Hb);
        launch_tf32(0, Hb, Dd, WR + OFF_PW1 + (size_t)l * Dd * 2 * Dd, 2 * Dd,
                    pw1_b + (size_t)l * 2 * Dd, nullptr, Y2, 2 * Dd, BTn, 2 * Dd, Dd);
        glu_tr<<<dim3(Tn / 32, Dd / 32, Bn), 256>>>(Y2, CV);
        dwconv_kernel<<<dim3(Tn / 128, Dd, Bn), 128>>>(
            CV, dw_w + (size_t)l * Dd * KWn, dw_b + (size_t)l * Dd, CV2);
        bn_stats<<<Dd, 256>>>(CV2);
        bn_tr<<<dim3(Tn / 32, Dd / 32, Bn), 256>>>(
            CV2, bn_g + (size_t)l * Dd, bn_b + (size_t)l * Dd, Hb);
        launch_tf32(2, Hb, Dd, WR + OFF_PW2 + (size_t)l * Dd * Dd, Dd,
                    pw2_b + (size_t)l * Dd, X, X, Dd, BTn, Dd, Dd);

        // ---- macaron FFN 2 (half residual) ----
        ln_kernel<true><<<BTn, 128>>>(X, lnS + 3 * Dd, lnB + 3 * Dd, Hb);
        launch_tf32(1, Hb, Dd, WR + OFF_FF2W1 + (size_t)l * Dd * DFFd, DFFd,
                    ff2_b1 + (size_t)l * DFFd, nullptr, FF, DFFd, BTn, DFFd, Dd);
        launch_tf32(3, FF, DFFd, WR + OFF_FF2W2 + (size_t)l * DFFd * Dd, Dd,
                    ff2_b2 + (size_t)l * Dd, X, X, Dd, BTn, Dd, DFFd);

        // ---- final per-layer LN (full precision) ----
        float* outp = (l == Ln - 1) ? (float*)d_out : X;
        ln_kernel<false><<<BTn, 128>>>(X, lnS + 4 * Dd, lnB + 4 * Dd, outp);
    }
}

// round 14
// speedup vs baseline: 1.0366x; 1.0366x over previous
#include <cuda_runtime.h>
#include <math.h>

// ---------------- problem constants ----------------
constexpr int Dd   = 512;
constexpr int Hn   = 8;
constexpr int DFFd = 2048;
constexpr int KWn  = 31;
constexpr int Ln   = 2;
constexpr int Bn   = 4;
constexpr int Tn   = 1024;
constexpr int DKn  = 64;
constexpr int Pn   = 2 * Tn - 1;      // 2047
constexpr int BTn  = Bn * Tn;         // 4096
constexpr float EPSf   = 1e-5f;
constexpr float SCALEf = 0.125f;      // 1/sqrt(64)

// rounded-weight scratch layout (floats)
constexpr size_t OFF_FF1W1 = 0;
constexpr size_t OFF_FF1W2 = OFF_FF1W1 + (size_t)Ln * Dd * DFFd;
constexpr size_t OFF_FF2W1 = OFF_FF1W2 + (size_t)Ln * DFFd * Dd;
constexpr size_t OFF_FF2W2 = OFF_FF2W1 + (size_t)Ln * Dd * DFFd;
constexpr size_t OFF_WQKV  = OFF_FF2W2 + (size_t)Ln * DFFd * Dd;   // [Ln][512][1536]
constexpr size_t OFF_WO    = OFF_WQKV + (size_t)Ln * Dd * 3 * Dd;
constexpr size_t OFF_WP    = OFF_WO + (size_t)Ln * Dd * Dd;
constexpr size_t OFF_PW1   = OFF_WP + (size_t)Ln * Dd * Dd;
constexpr size_t OFF_PW2   = OFF_PW1 + (size_t)Ln * Dd * 2 * Dd;
constexpr size_t OFF_BQKV  = OFF_PW2 + (size_t)Ln * Dd * Dd;       // [Ln][1536]
constexpr size_t WR_TOTAL  = OFF_BQKV + (size_t)Ln * 3 * Dd;

// GEMM dynamic smem: 3 stages x (A 128x32 + B 32x64) u32
constexpr int GEMM_STAGE_U32 = 128 * 32 + 32 * 64;     // 6144
constexpr int GEMM_SMEM = 3 * GEMM_STAGE_U32 * 4;      // 73728 B

// ---------------- device scratch (allocation-free) ----------------
__device__ float g_X  [BTn * Dd];
__device__ float g_H  [BTn * Dd];
__device__ float g_FF [BTn * DFFd];
__device__ float g_QKV[(size_t)BTn * 3 * Dd];
__device__ float g_P  [(size_t)Ln * Pn * Dd];   // per-layer pos projections
__device__ float g_PosR[Pn * Dd];               // tf32-rounded pos
__device__ float g_S  [(size_t)Bn * Hn * Tn * Tn];  // 128 MB scores
__device__ float g_CTX[BTn * Dd];
__device__ float g_Y2 [BTn * 2 * Dd];
__device__ float g_CV [Bn * Dd * Tn];
__device__ float g_CV2[Bn * Dd * Tn];
__device__ float g_mu [Dd];
__device__ float g_rstd[Dd];
__device__ float g_WR [WR_TOTAL];          // tf32-rounded weights

__device__ __forceinline__ float sigf(float x) { return 1.0f / (1.0f + expf(-x)); }

__device__ __forceinline__ unsigned f2tf32(float x) {
    unsigned u;
    asm("cvt.rna.tf32.f32 %0, %1;" : "=r"(u) : "f"(x));
    return u;
}
__device__ __forceinline__ float rnd_tf32(float x) { return __uint_as_float(f2tf32(x)); }

#define MMA_TF32(c0,c1,c2,c3,a0,a1,a2,a3,b0,b1)                              \
    asm volatile(                                                            \
        "mma.sync.aligned.m16n8k8.row.col.f32.tf32.tf32.f32 "                \
        "{%0,%1,%2,%3},{%4,%5,%6,%7},{%8,%9},{%0,%1,%2,%3};"                 \
        : "+f"(c0), "+f"(c1), "+f"(c2), "+f"(c3)                             \
        : "r"(a0), "r"(a1), "r"(a2), "r"(a3), "r"(b0), "r"(b1))

__device__ __forceinline__ void cpa16(unsigned dst, const void* src, int szbytes) {
    asm volatile("cp.async.cg.shared.global [%0], [%1], 16, %2;"
                 :: "r"(dst), "l"(src), "r"(szbytes));
}

// =======================================================================
// TF32 tensor-core GEMM, cp.async 3-stage pipeline, XOR-swizzled dyn smem.
// C = epilogue(A (MxK, lda) @ W (KxN, ldw) + bias)
// Tile: BM=128, BN=64, BK=32. 256 threads = 8 warps (4x2), warp 32x32.
// Inputs MUST be tf32-pre-rounded floats.
// MODE: 0 = (+bias, rnd), 1 = silu(+bias, rnd), 2 = res + (.), 3 = res + 0.5*(.)
// BMODE: 0 = plain; 1 = AV batch (z -> b,h of S@V); 2 = weight batch
//        (z selects W slab of Dd rows and C slab of Pn rows; pos projection).
// =======================================================================
template <int MODE, int BMODE>
__global__ void __launch_bounds__(256) tf32gemm(
    const float* __restrict__ A, int lda,
    const float* __restrict__ W, int ldw,
    const float* __restrict__ bias,
    const float* __restrict__ res,
    float* __restrict__ C, int ldc,
    int M, int N, int Kd)
{
    extern __shared__ unsigned gsm[];

    if (BMODE == 1) {
        int z = blockIdx.z;                       // z = b*8 + h
        A += (size_t)z * Tn * Tn;                 // S[b][h] (T x T)
        W += (size_t)(z >> 3) * Tn * ldw + (size_t)(z & 7) * DKn;
        C += (size_t)(z >> 3) * Tn * ldc + (size_t)(z & 7) * DKn;
    } else if (BMODE == 2) {
        int z = blockIdx.z;                       // layer index
        W += (size_t)z * Dd * ldw;
        C += (size_t)z * Pn * ldc;
    }

    const int bm = blockIdx.y * 128, bn = blockIdx.x * 64;
    const int tid  = threadIdx.x;
    const int warp = tid >> 5, lane = tid & 31;
    const int g = lane >> 2, t = lane & 3;
    const int wm = (warp >> 1) * 32, wn = (warp & 1) * 32;

    unsigned smBase = (unsigned)__cvta_generic_to_shared(gsm);

    auto loadTile = [&](int stage, int k0) {
        unsigned aOff = (unsigned)stage * GEMM_STAGE_U32;
#pragma unroll
        for (int i = 0; i < 4; i++) {
            int lin = i * 256 + tid;
            int row = lin >> 3, ck = lin & 7;
            int pc = ck ^ (row & 7);
            unsigned dst = smBase + (aOff + row * 32 + pc * 4) * 4;
            const float* src = A + (size_t)(bm + row) * lda + k0 + ck * 4;
            cpa16(dst, src, (bm + row < M) ? 16 : 0);
        }
        unsigned bOff = aOff + 4096;
#pragma unroll
        for (int i = 0; i < 2; i++) {
            int lin = i * 256 + tid;
            int kr = lin >> 4, c4 = lin & 15;
            int pc = c4 ^ (2 * (kr & 3));
            unsigned dst = smBase + (bOff + kr * 64 + pc * 4) * 4;
            const float* src = W + (size_t)(k0 + kr) * ldw + bn + c4 * 4;
            cpa16(dst, src, 16);
        }
        asm volatile("cp.async.commit_group;");
    };

    float acc[2][4][4] = {};

    int colB[4];
#pragma unroll
    for (int nt = 0; nt < 4; nt++) {
        int nb = wn + nt * 8 + g;
        colB[nt] = (((nb >> 2) ^ (2 * t)) << 2) | (nb & 3);
    }
    const int rA0 = wm + g, rA1 = wm + 16 + g;

    const int nk = Kd >> 5;
    loadTile(0, 0);
    loadTile(1, 32);

    for (int kb = 0; kb < nk; kb++) {
        if (kb + 2 < nk) {
            asm volatile("cp.async.wait_group 1;");
        } else {
            asm volatile("cp.async.wait_group 0;");
        }
        __syncthreads();

        const unsigned* Ac = gsm + (kb % 3) * GEMM_STAGE_U32;
        const unsigned* Bc = Ac + 4096;
#pragma unroll
        for (int kt = 0; kt < 4; kt++) {
            const int c0 = (((2 * kt) ^ g) << 2) | t;
            const int c1 = (((2 * kt + 1) ^ g) << 2) | t;
            const int kr = kt * 8 + t;
            unsigned a[2][4];
            a[0][0] = Ac[rA0 * 32 + c0];       a[0][1] = Ac[(rA0 + 8) * 32 + c0];
            a[0][2] = Ac[rA0 * 32 + c1];       a[0][3] = Ac[(rA0 + 8) * 32 + c1];
            a[1][0] = Ac[rA1 * 32 + c0];       a[1][1] = Ac[(rA1 + 8) * 32 + c0];
            a[1][2] = Ac[rA1 * 32 + c1];       a[1][3] = Ac[(rA1 + 8) * 32 + c1];
            unsigned b[4][2];
#pragma unroll
            for (int nt = 0; nt < 4; nt++) {
                b[nt][0] = Bc[kr * 64 + colB[nt]];
                b[nt][1] = Bc[(kr + 4) * 64 + colB[nt]];
            }
#pragma unroll
            for (int mt = 0; mt < 2; mt++)
#pragma unroll
                for (int nt = 0; nt < 4; nt++)
                    MMA_TF32(acc[mt][nt][0], acc[mt][nt][1], acc[mt][nt][2], acc[mt][nt][3],
                             a[mt][0], a[mt][1], a[mt][2], a[mt][3],
                             b[nt][0], b[nt][1]);
        }
        if (kb + 2 < nk) loadTile((kb + 2) % 3, (kb + 2) * 32);
    }

#pragma unroll
    for (int mt = 0; mt < 2; mt++) {
        int r0 = bm + wm + mt * 16 + g;
        int r1 = r0 + 8;
#pragma unroll
        for (int nt = 0; nt < 4; nt++) {
            int col = bn + wn + nt * 8 + 2 * t;
#pragma unroll
            for (int half = 0; half < 2; half++) {
                int row = half ? r1 : r0;
                if (row >= M) continue;
                float v0 = acc[mt][nt][half * 2 + 0];
                float v1 = acc[mt][nt][half * 2 + 1];
                if (bias) { v0 += bias[col]; v1 += bias[col + 1]; }
                if (MODE == 1) { v0 = v0 * sigf(v0); v1 = v1 * sigf(v1); }
                if (MODE == 0 || MODE == 1) { v0 = rnd_tf32(v0); v1 = rnd_tf32(v1); }
                if (MODE == 2) {
                    v0 = res[(size_t)row * ldc + col] + v0;
                    v1 = res[(size_t)row * ldc + col + 1] + v1;
                }
                if (MODE == 3) {
                    v0 = res[(size_t)row * ldc + col] + 0.5f * v0;
                    v1 = res[(size_t)row * ldc + col + 1] + 0.5f * v1;
                }
                *(float2*)&C[(size_t)row * ldc + col] = make_float2(v0, v1);
            }
        }
    }
}

// ---------------- LayerNorm: 128 threads, float4, warp shuffles ----------------
template <bool RND>
__global__ void __launch_bounds__(128) ln_kernel(
    const float* __restrict__ x, const float* __restrict__ s,
    const float* __restrict__ b, float* __restrict__ out)
{
    __shared__ float red[8];
    const int row = blockIdx.x;
    const int tid = threadIdx.x;
    const int lane = tid & 31, wid = tid >> 5;
    float4 v = ((const float4*)(x + (size_t)row * Dd))[tid];

    float s1 = v.x + v.y + v.z + v.w;
#pragma unroll
    for (int o = 16; o > 0; o >>= 1) s1 += __shfl_xor_sync(0xffffffffu, s1, o);
    if (lane == 0) red[wid] = s1;
    __syncthreads();
    float mean = (red[0] + red[1] + red[2] + red[3]) * (1.0f / Dd);

    float4 d;
    d.x = v.x - mean; d.y = v.y - mean; d.z = v.z - mean; d.w = v.w - mean;
    float s2 = d.x * d.x + d.y * d.y + d.z * d.z + d.w * d.w;
#pragma unroll
    for (int o = 16; o > 0; o >>= 1) s2 += __shfl_xor_sync(0xffffffffu, s2, o);
    if (lane == 0) red[4 + wid] = s2;
    __syncthreads();
    float rstd = rsqrtf((red[4] + red[5] + red[6] + red[7]) * (1.0f / Dd) + EPSf);

    float4 sc = ((const float4*)s)[tid];
    float4 bc = ((const float4*)b)[tid];
    float4 o4;
    o4.x = d.x * rstd * sc.x + bc.x;
    o4.y = d.y * rstd * sc.y + bc.y;
    o4.z = d.z * rstd * sc.z + bc.z;
    o4.w = d.w * rstd * sc.w + bc.w;
    if (RND) {
        o4.x = rnd_tf32(o4.x); o4.y = rnd_tf32(o4.y);
        o4.z = rnd_tf32(o4.z); o4.w = rnd_tf32(o4.w);
    }
    ((float4*)(out + (size_t)row * Dd))[tid] = o4;
}

// =======================================================================
// rel-pos attention scores on tensor cores (R8-verified).
// S[b,h,t,s] = ((q+u)·k[s] + (q+v)·p[T-1-t+s]) * SCALE
// =======================================================================
__global__ void __launch_bounds__(256) attn_scores(
    const float* __restrict__ Q, int ldq,
    const float* __restrict__ Km, int ldk,
    const float* __restrict__ Pm,
    const float* __restrict__ bu, const float* __restrict__ bvv,
    float* __restrict__ S)
{
    __shared__ unsigned qs[32][66], kt[32][66], pw[64][66];
    __shared__ float C1[32][33];
    __shared__ float C2[32][68];
    __shared__ float uk[32], vp[64];
    __shared__ float us[64], vs[64];

    const int z = blockIdx.z;
    const int b = z >> 3, h = z & 7;
    const int t0 = blockIdx.y << 5, s0 = blockIdx.x << 5;
    const int tid = threadIdx.x;

    if (tid < 16)
        ((float4*)us)[tid] = ((const float4*)(bu + h * 64))[tid];
    else if (tid < 32)
        ((float4*)vs)[tid - 16] = ((const float4*)(bvv + h * 64))[tid - 16];

    for (int i = tid; i < 512; i += 256) {
        int r = i >> 4, c = (i & 15) * 4;
        float4 q4 = *(const float4*)&Q[(size_t)(b * Tn + t0 + r) * ldq + h * 64 + c];
        qs[r][c + 0] = f2tf32(q4.x);
        qs[r][c + 1] = f2tf32(q4.y);
        qs[r][c + 2] = f2tf32(q4.z);
        qs[r][c + 3] = f2tf32(q4.w);
        float4 k4 = *(const float4*)&Km[(size_t)(b * Tn + s0 + r) * ldk + h * 64 + c];
        kt[r][c + 0] = f2tf32(k4.x);
        kt[r][c + 1] = f2tf32(k4.y);
        kt[r][c + 2] = f2tf32(k4.z);
        kt[r][c + 3] = f2tf32(k4.w);
    }
    const int base = (Tn - 32) - t0 + s0;     // in [0, P-63]
    for (int i = tid; i < 1024; i += 256) {
        int r = i >> 4, c = (i & 15) * 4;
        if (r < 63) {
            float4 p4 = *(const float4*)&Pm[(size_t)(base + r) * Dd + h * 64 + c];
            pw[r][c + 0] = f2tf32(p4.x);
            pw[r][c + 1] = f2tf32(p4.y);
            pw[r][c + 2] = f2tf32(p4.z);
            pw[r][c + 3] = f2tf32(p4.w);
        } else {
            pw[r][c + 0] = 0u; pw[r][c + 1] = 0u; pw[r][c + 2] = 0u; pw[r][c + 3] = 0u;
        }
    }
    __syncthreads();

    const int warp = tid >> 5, lane = tid & 31;
    const int g = lane >> 2, t = lane & 3;
    const int mw  = (warp >> 2) * 16;
    const int nwA = (warp & 3) * 8;
    const int nw2 = (warp & 3) * 16;

    float c1r[4] = {};
    float e[2][4] = {};
#pragma unroll
    for (int k0 = 0; k0 < 64; k0 += 8) {
        const int k = k0 + t;
        unsigned a0 = qs[mw + g][k],     a1 = qs[mw + 8 + g][k];
        unsigned a2 = qs[mw + g][k + 4], a3 = qs[mw + 8 + g][k + 4];
        unsigned b0 = kt[nwA + g][k],    b1 = kt[nwA + g][k + 4];
        MMA_TF32(c1r[0], c1r[1], c1r[2], c1r[3], a0, a1, a2, a3, b0, b1);
#pragma unroll
        for (int nt = 0; nt < 2; nt++) {
            int nb = nw2 + nt * 8 + g;
            unsigned p0 = pw[nb][k], p1 = pw[nb][k + 4];
            MMA_TF32(e[nt][0], e[nt][1], e[nt][2], e[nt][3], a0, a1, a2, a3, p0, p1);
        }
    }
    C1[mw + g][nwA + 2 * t]         = c1r[0];
    C1[mw + g][nwA + 2 * t + 1]     = c1r[1];
    C1[mw + 8 + g][nwA + 2 * t]     = c1r[2];
    C1[mw + 8 + g][nwA + 2 * t + 1] = c1r[3];
#pragma unroll
    for (int nt = 0; nt < 2; nt++) {
        int nb = nw2 + nt * 8;
        C2[mw + g][nb + 2 * t]         = e[nt][0];
        C2[mw + g][nb + 2 * t + 1]     = e[nt][1];
        C2[mw + 8 + g][nb + 2 * t]     = e[nt][2];
        C2[mw + 8 + g][nb + 2 * t + 1] = e[nt][3];
    }

    if (tid < 32) {
        float s = 0.f;
#pragma unroll 8
        for (int d = 0; d < 64; d++) s += us[d] * __uint_as_float(kt[tid][d]);
        uk[tid] = s;
    } else if (tid < 96) {
        int r = tid - 32;
        float s = 0.f;
#pragma unroll 8
        for (int d = 0; d < 64; d++) s += vs[d] * __uint_as_float(pw[r][d]);
        vp[r] = s;
    }
    __syncthreads();

    const int tl = tid >> 3, sl = (tid & 7) * 4;
    const int pr = 31 - tl + sl;
    float4 o4;
    o4.x = (C1[tl][sl + 0] + uk[sl + 0] + C2[tl][pr + 0] + vp[pr + 0]) * SCALEf;
    o4.y = (C1[tl][sl + 1] + uk[sl + 1] + C2[tl][pr + 1] + vp[pr + 1]) * SCALEf;
    o4.z = (C1[tl][sl + 2] + uk[sl + 2] + C2[tl][pr + 2] + vp[pr + 2]) * SCALEf;
    o4.w = (C1[tl][sl + 3] + uk[sl + 3] + C2[tl][pr + 3] + vp[pr + 3]) * SCALEf;
    *(float4*)&S[((size_t)z * Tn + (t0 + tl)) * Tn + (s0 + sl)] = o4;
}

// ---------------- row softmax over T=1024: warp-per-row, shuffle-only ----------------
__global__ void __launch_bounds__(256) softmax_kernel(float* __restrict__ S)
{
    const int tid  = threadIdx.x;
    const int warp = tid >> 5, lane = tid & 31;
    const size_t row = (size_t)blockIdx.x * 8 + warp;
    float4* p = (float4*)(S + row * Tn);

    float4 v[8];
    float m = -INFINITY;
#pragma unroll
    for (int j = 0; j < 8; j++) {
        v[j] = p[j * 32 + lane];
        m = fmaxf(m, fmaxf(fmaxf(v[j].x, v[j].y), fmaxf(v[j].z, v[j].w)));
    }
#pragma unroll
    for (int o = 16; o > 0; o >>= 1) m = fmaxf(m, __shfl_xor_sync(0xffffffffu, m, o));
    float s = 0.f;
#pragma unroll
    for (int j = 0; j < 8; j++) {
        v[j].x = expf(v[j].x - m); v[j].y = expf(v[j].y - m);
        v[j].z = expf(v[j].z - m); v[j].w = expf(v[j].w - m);
        s += v[j].x + v[j].y + v[j].z + v[j].w;
    }
#pragma unroll
    for (int o = 16; o > 0; o >>= 1) s += __shfl_xor_sync(0xffffffffu, s, o);
    float inv = 1.0f / s;
#pragma unroll
    for (int j = 0; j < 8; j++) {
        float4 o4;
        o4.x = rnd_tf32(v[j].x * inv); o4.y = rnd_tf32(v[j].y * inv);
        o4.z = rnd_tf32(v[j].z * inv); o4.w = rnd_tf32(v[j].w * inv);
        p[j * 32 + lane] = o4;
    }
}

// ---------------- GLU + transpose (B,T,2D) -> (B,D,T), tiled ----------------
__global__ void __launch_bounds__(256) glu_tr(const float* __restrict__ Y2,
                                              float* __restrict__ CV)
{
    __shared__ float tile[32][33];
    const int b = blockIdx.z;
    const int d0 = blockIdx.y * 32, t0 = blockIdx.x * 32;
    const int tid = threadIdx.x;
    const int rr = tid >> 5, cc = tid & 31;
#pragma unroll
    for (int i = 0; i < 4; i++) {
        int tl = rr + i * 8;
        size_t base = (size_t)(b * Tn + t0 + tl) * (2 * Dd) + d0 + cc;
        float a = Y2[base];
        float g = Y2[base + Dd];
        tile[tl][cc] = a * sigf(g);
    }
    __syncthreads();
#pragma unroll
    for (int i = 0; i < 4; i++) {
        int dl = rr + i * 8;
        CV[((size_t)b * Dd + d0 + dl) * Tn + t0 + cc] = tile[cc][dl];
    }
}

// ---------------- depthwise conv K=31, pad 15 ----------------
__global__ void __launch_bounds__(128) dwconv_kernel(
    const float* __restrict__ CV, const float* __restrict__ w,
    const float* __restrict__ bias, float* __restrict__ out)
{
    __shared__ float sin_[128 + 30];
    __shared__ float sw[31];
    const int t0 = blockIdx.x * 128;
    const int d = blockIdx.y;
    const int b = blockIdx.z;
    const float* ip = CV + ((size_t)b * Dd + d) * Tn;
    const int tid = threadIdx.x;
    for (int i = tid; i < 158; i += 128) {
        int t = t0 - 15 + i;
        sin_[i] = (t >= 0 && t < Tn) ? ip[t] : 0.0f;
    }
    if (tid < 31) sw[tid] = w[d * KWn + tid];
    __syncthreads();
    float acc = bias[d];
#pragma unroll
    for (int k = 0; k < 31; k++) acc += sin_[tid + k] * sw[k];
    out[((size_t)b * Dd + d) * Tn + t0 + tid] = acc;
}

// ---------------- BatchNorm stats ----------------
__global__ void __launch_bounds__(256) bn_stats(const float* __restrict__ y)
{
    __shared__ float rs[256], rs2[256];
    const int d = blockIdx.x;
    const int tid = threadIdx.x;
    float s = 0.f, s2 = 0.f;
    for (int b = 0; b < Bn; b++) {
        const float* p = y + ((size_t)b * Dd + d) * Tn;
        for (int t = tid; t < Tn; t += 256) {
            float v = p[t];
            s += v;
            s2 += v * v;
        }
    }
    rs[tid] = s; rs2[tid] = s2;
    __syncthreads();
    for (int o = 128; o > 0; o >>= 1) {
        if (tid < o) { rs[tid] += rs[tid + o]; rs2[tid] += rs2[tid + o]; }
        __syncthreads();
    }
    if (tid == 0) {
        float mu = rs[0] * (1.0f / (Bn * Tn));
        float var = rs2[0] * (1.0f / (Bn * Tn)) - mu * mu;
        g_mu[d] = mu;
        g_rstd[d] = rsqrtf(var + EPSf);
    }
}

// ---------------- BN apply + SiLU + transpose -> (B,T,D), tf32-rounded ----------------
__global__ void __launch_bounds__(256) bn_tr(
    const float* __restrict__ y, const float* __restrict__ g,
    const float* __restrict__ bt, float* __restrict__ out)
{
    __shared__ float tile[32][33];
    const int b = blockIdx.z;
    const int d0 = blockIdx.y * 32, t0 = blockIdx.x * 32;
    const int tid = threadIdx.x;
    const int rr = tid >> 5, cc = tid & 31;
#pragma unroll
    for (int i = 0; i < 4; i++) {
        int dl = rr + i * 8;
        int d = d0 + dl;
        float v = y[((size_t)b * Dd + d) * Tn + t0 + cc];
        v = (v - g_mu[d]) * g_rstd[d] * g[d] + bt[d];
        v = v * sigf(v);
        tile[dl][cc] = rnd_tf32(v);
    }
    __syncthreads();
#pragma unroll
    for (int i = 0; i < 4; i++) {
        int tl = rr + i * 8;
        out[(size_t)(b * Tn + t0 + tl) * Dd + d0 + cc] = tile[cc][tl];
    }
}

// ---------------- copy ----------------
__global__ void __launch_bounds__(256) copy_kernel(const float* __restrict__ in,
                                                   float* __restrict__ out, int n)
{
    int i = blockIdx.x * 256 + threadIdx.x;
    if (i < n) out[i] = in[i];
}

// ---------------- consolidated tf32 rounding / packing prologue ----------------
constexpr int NSEG = 15;
struct RPack {
    const float* src[NSEG];
    float*       dst[NSEG];
    int n[NSEG];
    int cols[NSEG];
    int dstld[NSEG];
};
__global__ void __launch_bounds__(256) round_multi(RPack p)
{
    int sgi = blockIdx.y;
    int i = blockIdx.x * 256 + threadIdx.x;
    if (i >= p.n[sgi]) return;
    int r = i / p.cols[sgi], c = i - r * p.cols[sgi];
    p.dst[sgi][(size_t)r * p.dstld[sgi] + c] = rnd_tf32(p.src[sgi][i]);
}

// ---------------- host-side launch helper ----------------
static void launch_tf32(int mode,
                        const float* A, int lda,
                        const float* W, int ldw,
                        const float* bias, const float* res,
                        float* C, int ldc,
                        int M, int N, int Kd)
{
    dim3 g(N / 64, (M + 127) / 128, 1);
    switch (mode) {
        case 0: tf32gemm<0, 0><<<g, 256, GEMM_SMEM>>>(A, lda, W, ldw, bias, res, C, ldc, M, N, Kd); break;
        case 1: tf32gemm<1, 0><<<g, 256, GEMM_SMEM>>>(A, lda, W, ldw, bias, res, C, ldc, M, N, Kd); break;
        case 2: tf32gemm<2, 0><<<g, 256, GEMM_SMEM>>>(A, lda, W, ldw, bias, res, C, ldc, M, N, Kd); break;
        case 3: tf32gemm<3, 0><<<g, 256, GEMM_SMEM>>>(A, lda, W, ldw, bias, res, C, ldc, M, N, Kd); break;
    }
}

extern "C" void kernel_launch(void* const* d_in, const int* in_sizes, int n_in,
                              void* d_out, int out_size)
{
    const float* in_x   = (const float*)d_in[0];
    const float* pos    = (const float*)d_in[1];
    const float* ln_s   = (const float*)d_in[2];
    const float* ln_b   = (const float*)d_in[3];
    const float* ff1_w1 = (const float*)d_in[4];
    const float* ff1_b1 = (const float*)d_in[5];
    const float* ff1_w2 = (const float*)d_in[6];
    const float* ff1_b2 = (const float*)d_in[7];
    const float* ff2_w1 = (const float*)d_in[8];
    const float* ff2_b1 = (const float*)d_in[9];
    const float* ff2_w2 = (const float*)d_in[10];
    const float* ff2_b2 = (const float*)d_in[11];
    const float* wq     = (const float*)d_in[12];
    const float* bq     = (const float*)d_in[13];
    const float* wk     = (const float*)d_in[14];
    const float* bk     = (const float*)d_in[15];
    const float* wv     = (const float*)d_in[16];
    const float* bv     = (const float*)d_in[17];
    const float* wp     = (const float*)d_in[18];
    const float* wo     = (const float*)d_in[19];
    const float* bo     = (const float*)d_in[20];
    const float* bias_u = (const float*)d_in[21];
    const float* bias_v = (const float*)d_in[22];
    const float* pw1_w  = (const float*)d_in[23];
    const float* pw1_b  = (const float*)d_in[24];
    const float* dw_w   = (const float*)d_in[25];
    const float* dw_b   = (const float*)d_in[26];
    const float* bn_g   = (const float*)d_in[27];
    const float* bn_b   = (const float*)d_in[28];
    const float* pw2_w  = (const float*)d_in[29];
    const float* pw2_b  = (const float*)d_in[30];
    (void)in_sizes; (void)n_in; (void)out_size;

    float *X, *Hb, *FF, *QKV, *Pb, *PosR, *Sb, *CTX, *Y2, *CV, *CV2, *WR;
    cudaGetSymbolAddress((void**)&X,    g_X);
    cudaGetSymbolAddress((void**)&Hb,   g_H);
    cudaGetSymbolAddress((void**)&FF,   g_FF);
    cudaGetSymbolAddress((void**)&QKV,  g_QKV);
    cudaGetSymbolAddress((void**)&Pb,   g_P);
    cudaGetSymbolAddress((void**)&PosR, g_PosR);
    cudaGetSymbolAddress((void**)&Sb,   g_S);
    cudaGetSymbolAddress((void**)&CTX,  g_CTX);
    cudaGetSymbolAddress((void**)&Y2,   g_Y2);
    cudaGetSymbolAddress((void**)&CV,   g_CV);
    cudaGetSymbolAddress((void**)&CV2,  g_CV2);
    cudaGetSymbolAddress((void**)&WR,   g_WR);

    cudaFuncSetAttribute((const void*)tf32gemm<0, 0>, cudaFuncAttributeMaxDynamicSharedMemorySize, GEMM_SMEM);
    cudaFuncSetAttribute((const void*)tf32gemm<1, 0>, cudaFuncAttributeMaxDynamicSharedMemorySize, GEMM_SMEM);
    cudaFuncSetAttribute((const void*)tf32gemm<2, 0>, cudaFuncAttributeMaxDynamicSharedMemorySize, GEMM_SMEM);
    cudaFuncSetAttribute((const void*)tf32gemm<3, 0>, cudaFuncAttributeMaxDynamicSharedMemorySize, GEMM_SMEM);
    cudaFuncSetAttribute((const void*)tf32gemm<0, 1>, cudaFuncAttributeMaxDynamicSharedMemorySize, GEMM_SMEM);
    cudaFuncSetAttribute((const void*)tf32gemm<0, 2>, cudaFuncAttributeMaxDynamicSharedMemorySize, GEMM_SMEM);

    // consolidated tf32 rounding + QKV weight/bias interleave
    {
        RPack p;
        int i = 0;
        auto seg = [&](const float* s, float* d, size_t n, int cols, int ld) {
            p.src[i] = s; p.dst[i] = d; p.n[i] = (int)n; p.cols[i] = cols; p.dstld[i] = ld; i++;
        };
        seg(ff1_w1, WR + OFF_FF1W1, (size_t)Ln * Dd * DFFd, (int)((size_t)Ln * Dd * DFFd), (int)((size_t)Ln * Dd * DFFd));
        seg(ff1_w2, WR + OFF_FF1W2, (size_t)Ln * DFFd * Dd, (int)((size_t)Ln * DFFd * Dd), (int)((size_t)Ln * DFFd * Dd));
        seg(ff2_w1, WR + OFF_FF2W1, (size_t)Ln * Dd * DFFd, (int)((size_t)Ln * Dd * DFFd), (int)((size_t)Ln * Dd * DFFd));
        seg(ff2_w2, WR + OFF_FF2W2, (size_t)Ln * DFFd * Dd, (int)((size_t)Ln * DFFd * Dd), (int)((size_t)Ln * DFFd * Dd));
        seg(wo,     WR + OFF_WO,    (size_t)Ln * Dd * Dd, (int)((size_t)Ln * Dd * Dd), (int)((size_t)Ln * Dd * Dd));
        seg(wp,     WR + OFF_WP,    (size_t)Ln * Dd * Dd, (int)((size_t)Ln * Dd * Dd), (int)((size_t)Ln * Dd * Dd));
        seg(pw1_w,  WR + OFF_PW1,   (size_t)Ln * Dd * 2 * Dd, (int)((size_t)Ln * Dd * 2 * Dd), (int)((size_t)Ln * Dd * 2 * Dd));
        seg(pw2_w,  WR + OFF_PW2,   (size_t)Ln * Dd * Dd, (int)((size_t)Ln * Dd * Dd), (int)((size_t)Ln * Dd * Dd));
        seg(pos,    PosR,           (size_t)Pn * Dd, (int)((size_t)Pn * Dd), (int)((size_t)Pn * Dd));
        seg(wq, WR + OFF_WQKV + 0,        (size_t)Ln * Dd * Dd, Dd, 3 * Dd);
        seg(wk, WR + OFF_WQKV + Dd,       (size_t)Ln * Dd * Dd, Dd, 3 * Dd);
        seg(wv, WR + OFF_WQKV + 2 * Dd,   (size_t)Ln * Dd * Dd, Dd, 3 * Dd);
        seg(bq, WR + OFF_BQKV + 0,        (size_t)Ln * Dd, Dd, 3 * Dd);
        seg(bk, WR + OFF_BQKV + Dd,       (size_t)Ln * Dd, Dd, 3 * Dd);
        seg(bv, WR + OFF_BQKV + 2 * Dd,   (size_t)Ln * Dd, Dd, 3 * Dd);
        round_multi<<<dim3(((size_t)Ln * Dd * DFFd + 255) / 256, NSEG), 256>>>(p);
    }

    copy_kernel<<<(BTn * Dd) / 256, 256>>>(in_x, X, BTn * Dd);

    // pos projections for BOTH layers, hoisted + batched (inputs-only dependence)
    tf32gemm<0, 2><<<dim3(Dd / 64, (Pn + 127) / 128, Ln), 256, GEMM_SMEM>>>(
        PosR, Dd, WR + OFF_WP, Dd, nullptr, nullptr, Pb, Dd, Pn, Dd, Dd);

    for (int l = 0; l < Ln; ++l) {
        const float* lnS = ln_s + (size_t)l * 5 * Dd;
        const float* lnB = ln_b + (size_t)l * 5 * Dd;

        // ---- macaron FFN 1 (half residual) ----
        ln_kernel<true><<<BTn, 128>>>(X, lnS, lnB, Hb);
        launch_tf32(1, Hb, Dd, WR + OFF_FF1W1 + (size_t)l * Dd * DFFd, DFFd,
                    ff1_b1 + (size_t)l * DFFd, nullptr, FF, DFFd, BTn, DFFd, Dd);
        launch_tf32(3, FF, DFFd, WR + OFF_FF1W2 + (size_t)l * DFFd * Dd, Dd,
                    ff1_b2 + (size_t)l * Dd, X, X, Dd, BTn, Dd, DFFd);

        // ---- rel-pos MHSA ----
        ln_kernel<true><<<BTn, 128>>>(X, lnS + Dd, lnB + Dd, Hb);
        launch_tf32(0, Hb, Dd, WR + OFF_WQKV + (size_t)l * Dd * 3 * Dd, 3 * Dd,
                    WR + OFF_BQKV + (size_t)l * 3 * Dd, nullptr, QKV, 3 * Dd, BTn, 3 * Dd, Dd);

        attn_scores<<<dim3(Tn / 32, Tn / 32, Bn * Hn), 256>>>(
            QKV, 3 * Dd, QKV + Dd, 3 * Dd, Pb + (size_t)l * Pn * Dd,
            bias_u + (size_t)l * Hn * DKn, bias_v + (size_t)l * Hn * DKn, Sb);
        softmax_kernel<<<Bn * Hn * Tn / 8, 256>>>(Sb);

        tf32gemm<0, 1><<<dim3(1, Tn / 128, Bn * Hn), 256, GEMM_SMEM>>>(
            Sb, Tn, QKV + 2 * Dd, 3 * Dd, nullptr, nullptr, CTX, Dd, Tn, DKn, Tn);

        launch_tf32(2, CTX, Dd, WR + OFF_WO + (size_t)l * Dd * Dd, Dd,
                    bo + (size_t)l * Dd, X, X, Dd, BTn, Dd, Dd);

        // ---- conv module ----
        ln_kernel<true><<<BTn, 128>>>(X, lnS + 2 * Dd, lnB + 2 * Dd, Hb);
        launch_tf32(0, Hb, Dd, WR + OFF_PW1 + (size_t)l * Dd * 2 * Dd, 2 * Dd,
                    pw1_b + (size_t)l * 2 * Dd, nullptr, Y2, 2 * Dd, BTn, 2 * Dd, Dd);
        glu_tr<<<dim3(Tn / 32, Dd / 32, Bn), 256>>>(Y2, CV);
        dwconv_kernel<<<dim3(Tn / 128, Dd, Bn), 128>>>(
            CV, dw_w + (size_t)l * Dd * KWn, dw_b + (size_t)l * Dd, CV2);
        bn_stats<<<Dd, 256>>>(CV2);
        bn_tr<<<dim3(Tn / 32, Dd / 32, Bn), 256>>>(
            CV2, bn_g + (size_t)l * Dd, bn_b + (size_t)l * Dd, Hb);
        launch_tf32(2, Hb, Dd, WR + OFF_PW2 + (size_t)l * Dd * Dd, Dd,
                    pw2_b + (size_t)l * Dd, X, X, Dd, BTn, Dd, Dd);

        // ---- macaron FFN 2 (half residual) ----
        ln_kernel<true><<<BTn, 128>>>(X, lnS + 3 * Dd, lnB + 3 * Dd, Hb);
        launch_tf32(1, Hb, Dd, WR + OFF_FF2W1 + (size_t)l * Dd * DFFd, DFFd,
                    ff2_b1 + (size_t)l * DFFd, nullptr, FF, DFFd, BTn, DFFd, Dd);
        launch_tf32(3, FF, DFFd, WR + OFF_FF2W2 + (size_t)l * DFFd * Dd, Dd,
                    ff2_b2 + (size_t)l * Dd, X, X, Dd, BTn, Dd, DFFd);

        // ---- final per-layer LN (full precision) ----
        float* outp = (l == Ln - 1) ? (float*)d_out : X;
        ln_kernel<false><<<BTn, 128>>>(X, lnS + 4 * Dd, lnB + 4 * Dd, outp);
    }
}

// round 15
// speedup vs baseline: 1.0461x; 1.0092x over previous
#include <cuda_runtime.h>
#include <math.h>

// ---------------- problem constants ----------------
constexpr int Dd   = 512;
constexpr int Hn   = 8;
constexpr int DFFd = 2048;
constexpr int KWn  = 31;
constexpr int Ln   = 2;
constexpr int Bn   = 4;
constexpr int Tn   = 1024;
constexpr int DKn  = 64;
constexpr int Pn   = 2 * Tn - 1;      // 2047
constexpr int BTn  = Bn * Tn;         // 4096
constexpr float EPSf   = 1e-5f;
constexpr float SCALEf = 0.125f;      // 1/sqrt(64)

// rounded-weight scratch layout (floats)
constexpr size_t OFF_FF1W1 = 0;
constexpr size_t OFF_FF1W2 = OFF_FF1W1 + (size_t)Ln * Dd * DFFd;
constexpr size_t OFF_FF2W1 = OFF_FF1W2 + (size_t)Ln * DFFd * Dd;
constexpr size_t OFF_FF2W2 = OFF_FF2W1 + (size_t)Ln * Dd * DFFd;
constexpr size_t OFF_WQKV  = OFF_FF2W2 + (size_t)Ln * DFFd * Dd;   // [Ln][512][1536]
constexpr size_t OFF_WO    = OFF_WQKV + (size_t)Ln * Dd * 3 * Dd;
constexpr size_t OFF_WP    = OFF_WO + (size_t)Ln * Dd * Dd;
constexpr size_t OFF_PW1   = OFF_WP + (size_t)Ln * Dd * Dd;
constexpr size_t OFF_PW2   = OFF_PW1 + (size_t)Ln * Dd * 2 * Dd;
constexpr size_t OFF_BQKV  = OFF_PW2 + (size_t)Ln * Dd * Dd;       // [Ln][1536]
constexpr size_t WR_TOTAL  = OFF_BQKV + (size_t)Ln * 3 * Dd;

// GEMM dynamic smem: 3 stages x (A 128x32 + B 32x64) u32
constexpr int GEMM_STAGE_U32 = 128 * 32 + 32 * 64;     // 6144
constexpr int GEMM_SMEM = 3 * GEMM_STAGE_U32 * 4;      // 73728 B

// ---------------- device scratch (allocation-free) ----------------
__device__ float g_X  [BTn * Dd];
__device__ float g_H  [BTn * Dd];
__device__ float g_FF [BTn * DFFd];
__device__ float g_QKV[(size_t)BTn * 3 * Dd];
__device__ float g_P  [(size_t)Ln * Pn * Dd];   // per-layer pos projections
__device__ float g_PosR[Pn * Dd];               // tf32-rounded pos
__device__ float g_S  [(size_t)Bn * Hn * Tn * Tn];  // 128 MB scores
__device__ float g_CTX[BTn * Dd];
__device__ float g_Y2 [BTn * 2 * Dd];
__device__ float g_CV2[Bn * Dd * Tn];
__device__ float g_part[32][2][Dd];             // BN partials: [b*8+tblk][sum|sq][d]
__device__ float g_mu [Dd];
__device__ float g_rstd[Dd];
__device__ float g_WR [WR_TOTAL];          // tf32-rounded weights

__device__ __forceinline__ float sigf(float x) { return 1.0f / (1.0f + expf(-x)); }

__device__ __forceinline__ unsigned f2tf32(float x) {
    unsigned u;
    asm("cvt.rna.tf32.f32 %0, %1;" : "=r"(u) : "f"(x));
    return u;
}
__device__ __forceinline__ float rnd_tf32(float x) { return __uint_as_float(f2tf32(x)); }

#define MMA_TF32(c0,c1,c2,c3,a0,a1,a2,a3,b0,b1)                              \
    asm volatile(                                                            \
        "mma.sync.aligned.m16n8k8.row.col.f32.tf32.tf32.f32 "                \
        "{%0,%1,%2,%3},{%4,%5,%6,%7},{%8,%9},{%0,%1,%2,%3};"                 \
        : "+f"(c0), "+f"(c1), "+f"(c2), "+f"(c3)                             \
        : "r"(a0), "r"(a1), "r"(a2), "r"(a3), "r"(b0), "r"(b1))

__device__ __forceinline__ void cpa16(unsigned dst, const void* src, int szbytes) {
    asm volatile("cp.async.cg.shared.global [%0], [%1], 16, %2;"
                 :: "r"(dst), "l"(src), "r"(szbytes));
}

// =======================================================================
// TF32 tensor-core GEMM, cp.async 3-stage pipeline, XOR-swizzled dyn smem.
// C = epilogue(A (MxK, lda) @ W (KxN, ldw) + bias)
// Tile: BM=128, BN=64, BK=32. 256 threads = 8 warps (4x2), warp 32x32.
// Inputs MUST be tf32-pre-rounded floats.
// MODE: 0 = (+bias, rnd), 1 = silu(+bias, rnd), 2 = res + (.), 3 = res + 0.5*(.)
// BMODE: 0 = plain; 1 = AV batch (z -> b,h of S@V); 2 = weight batch (pos proj).
// =======================================================================
template <int MODE, int BMODE>
__global__ void __launch_bounds__(256) tf32gemm(
    const float* __restrict__ A, int lda,
    const float* __restrict__ W, int ldw,
    const float* __restrict__ bias,
    const float* __restrict__ res,
    float* __restrict__ C, int ldc,
    int M, int N, int Kd)
{
    extern __shared__ unsigned gsm[];

    if (BMODE == 1) {
        int z = blockIdx.z;                       // z = b*8 + h
        A += (size_t)z * Tn * Tn;                 // S[b][h] (T x T)
        W += (size_t)(z >> 3) * Tn * ldw + (size_t)(z & 7) * DKn;
        C += (size_t)(z >> 3) * Tn * ldc + (size_t)(z & 7) * DKn;
    } else if (BMODE == 2) {
        int z = blockIdx.z;                       // layer index
        W += (size_t)z * Dd * ldw;
        C += (size_t)z * Pn * ldc;
    }

    const int bm = blockIdx.y * 128, bn = blockIdx.x * 64;
    const int tid  = threadIdx.x;
    const int warp = tid >> 5, lane = tid & 31;
    const int g = lane >> 2, t = lane & 3;
    const int wm = (warp >> 1) * 32, wn = (warp & 1) * 32;

    unsigned smBase = (unsigned)__cvta_generic_to_shared(gsm);

    auto loadTile = [&](int stage, int k0) {
        unsigned aOff = (unsigned)stage * GEMM_STAGE_U32;
#pragma unroll
        for (int i = 0; i < 4; i++) {
            int lin = i * 256 + tid;
            int row = lin >> 3, ck = lin & 7;
            int pc = ck ^ (row & 7);
            unsigned dst = smBase + (aOff + row * 32 + pc * 4) * 4;
            const float* src = A + (size_t)(bm + row) * lda + k0 + ck * 4;
            cpa16(dst, src, (bm + row < M) ? 16 : 0);
        }
        unsigned bOff = aOff + 4096;
#pragma unroll
        for (int i = 0; i < 2; i++) {
            int lin = i * 256 + tid;
            int kr = lin >> 4, c4 = lin & 15;
            int pc = c4 ^ (2 * (kr & 3));
            unsigned dst = smBase + (bOff + kr * 64 + pc * 4) * 4;
            const float* src = W + (size_t)(k0 + kr) * ldw + bn + c4 * 4;
            cpa16(dst, src, 16);
        }
        asm volatile("cp.async.commit_group;");
    };

    float acc[2][4][4] = {};

    int colB[4];
#pragma unroll
    for (int nt = 0; nt < 4; nt++) {
        int nb = wn + nt * 8 + g;
        colB[nt] = (((nb >> 2) ^ (2 * t)) << 2) | (nb & 3);
    }
    const int rA0 = wm + g, rA1 = wm + 16 + g;

    const int nk = Kd >> 5;
    loadTile(0, 0);
    loadTile(1, 32);

    for (int kb = 0; kb < nk; kb++) {
        if (kb + 2 < nk) {
            asm volatile("cp.async.wait_group 1;");
        } else {
            asm volatile("cp.async.wait_group 0;");
        }
        __syncthreads();

        const unsigned* Ac = gsm + (kb % 3) * GEMM_STAGE_U32;
        const unsigned* Bc = Ac + 4096;
#pragma unroll
        for (int kt = 0; kt < 4; kt++) {
            const int c0 = (((2 * kt) ^ g) << 2) | t;
            const int c1 = (((2 * kt + 1) ^ g) << 2) | t;
            const int kr = kt * 8 + t;
            unsigned a[2][4];
            a[0][0] = Ac[rA0 * 32 + c0];       a[0][1] = Ac[(rA0 + 8) * 32 + c0];
            a[0][2] = Ac[rA0 * 32 + c1];       a[0][3] = Ac[(rA0 + 8) * 32 + c1];
            a[1][0] = Ac[rA1 * 32 + c0];       a[1][1] = Ac[(rA1 + 8) * 32 + c0];
            a[1][2] = Ac[rA1 * 32 + c1];       a[1][3] = Ac[(rA1 + 8) * 32 + c1];
            unsigned b[4][2];
#pragma unroll
            for (int nt = 0; nt < 4; nt++) {
                b[nt][0] = Bc[kr * 64 + colB[nt]];
                b[nt][1] = Bc[(kr + 4) * 64 + colB[nt]];
            }
#pragma unroll
            for (int mt = 0; mt < 2; mt++)
#pragma unroll
                for (int nt = 0; nt < 4; nt++)
                    MMA_TF32(acc[mt][nt][0], acc[mt][nt][1], acc[mt][nt][2], acc[mt][nt][3],
                             a[mt][0], a[mt][1], a[mt][2], a[mt][3],
                             b[nt][0], b[nt][1]);
        }
        if (kb + 2 < nk) loadTile((kb + 2) % 3, (kb + 2) * 32);
    }

#pragma unroll
    for (int mt = 0; mt < 2; mt++) {
        int r0 = bm + wm + mt * 16 + g;
        int r1 = r0 + 8;
#pragma unroll
        for (int nt = 0; nt < 4; nt++) {
            int col = bn + wn + nt * 8 + 2 * t;
#pragma unroll
            for (int half = 0; half < 2; half++) {
                int row = half ? r1 : r0;
                if (row >= M) continue;
                float v0 = acc[mt][nt][half * 2 + 0];
                float v1 = acc[mt][nt][half * 2 + 1];
                if (bias) { v0 += bias[col]; v1 += bias[col + 1]; }
                if (MODE == 1) { v0 = v0 * sigf(v0); v1 = v1 * sigf(v1); }
                if (MODE == 0 || MODE == 1) { v0 = rnd_tf32(v0); v1 = rnd_tf32(v1); }
                if (MODE == 2) {
                    v0 = res[(size_t)row * ldc + col] + v0;
                    v1 = res[(size_t)row * ldc + col + 1] + v1;
                }
                if (MODE == 3) {
                    v0 = res[(size_t)row * ldc + col] + 0.5f * v0;
                    v1 = res[(size_t)row * ldc + col + 1] + 0.5f * v1;
                }
                *(float2*)&C[(size_t)row * ldc + col] = make_float2(v0, v1);
            }
        }
    }
}

// ---------------- LayerNorm: 128 threads, float4, warp shuffles ----------------
template <bool RND>
__global__ void __launch_bounds__(128) ln_kernel(
    const float* __restrict__ x, const float* __restrict__ s,
    const float* __restrict__ b, float* __restrict__ out)
{
    __shared__ float red[8];
    const int row = blockIdx.x;
    const int tid = threadIdx.x;
    const int lane = tid & 31, wid = tid >> 5;
    float4 v = ((const float4*)(x + (size_t)row * Dd))[tid];

    float s1 = v.x + v.y + v.z + v.w;
#pragma unroll
    for (int o = 16; o > 0; o >>= 1) s1 += __shfl_xor_sync(0xffffffffu, s1, o);
    if (lane == 0) red[wid] = s1;
    __syncthreads();
    float mean = (red[0] + red[1] + red[2] + red[3]) * (1.0f / Dd);

    float4 d;
    d.x = v.x - mean; d.y = v.y - mean; d.z = v.z - mean; d.w = v.w - mean;
    float s2 = d.x * d.x + d.y * d.y + d.z * d.z + d.w * d.w;
#pragma unroll
    for (int o = 16; o > 0; o >>= 1) s2 += __shfl_xor_sync(0xffffffffu, s2, o);
    if (lane == 0) red[4 + wid] = s2;
    __syncthreads();
    float rstd = rsqrtf((red[4] + red[5] + red[6] + red[7]) * (1.0f / Dd) + EPSf);

    float4 sc = ((const float4*)s)[tid];
    float4 bc = ((const float4*)b)[tid];
    float4 o4;
    o4.x = d.x * rstd * sc.x + bc.x;
    o4.y = d.y * rstd * sc.y + bc.y;
    o4.z = d.z * rstd * sc.z + bc.z;
    o4.w = d.w * rstd * sc.w + bc.w;
    if (RND) {
        o4.x = rnd_tf32(o4.x); o4.y = rnd_tf32(o4.y);
        o4.z = rnd_tf32(o4.z); o4.w = rnd_tf32(o4.w);
    }
    ((float4*)(out + (size_t)row * Dd))[tid] = o4;
}

// =======================================================================
// rel-pos attention scores on tensor cores (R8-verified).
// S[b,h,t,s] = ((q+u)·k[s] + (q+v)·p[T-1-t+s]) * SCALE
// =======================================================================
__global__ void __launch_bounds__(256) attn_scores(
    const float* __restrict__ Q, int ldq,
    const float* __restrict__ Km, int ldk,
    const float* __restrict__ Pm,
    const float* __restrict__ bu, const float* __restrict__ bvv,
    float* __restrict__ S)
{
    __shared__ unsigned qs[32][66], kt[32][66], pw[64][66];
    __shared__ float C1[32][33];
    __shared__ float C2[32][68];
    __shared__ float uk[32], vp[64];
    __shared__ float us[64], vs[64];

    const int z = blockIdx.z;
    const int b = z >> 3, h = z & 7;
    const int t0 = blockIdx.y << 5, s0 = blockIdx.x << 5;
    const int tid = threadIdx.x;

    if (tid < 16)
        ((float4*)us)[tid] = ((const float4*)(bu + h * 64))[tid];
    else if (tid < 32)
        ((float4*)vs)[tid - 16] = ((const float4*)(bvv + h * 64))[tid - 16];

    for (int i = tid; i < 512; i += 256) {
        int r = i >> 4, c = (i & 15) * 4;
        float4 q4 = *(const float4*)&Q[(size_t)(b * Tn + t0 + r) * ldq + h * 64 + c];
        qs[r][c + 0] = f2tf32(q4.x);
        qs[r][c + 1] = f2tf32(q4.y);
        qs[r][c + 2] = f2tf32(q4.z);
        qs[r][c + 3] = f2tf32(q4.w);
        float4 k4 = *(const float4*)&Km[(size_t)(b * Tn + s0 + r) * ldk + h * 64 + c];
        kt[r][c + 0] = f2tf32(k4.x);
        kt[r][c + 1] = f2tf32(k4.y);
        kt[r][c + 2] = f2tf32(k4.z);
        kt[r][c + 3] = f2tf32(k4.w);
    }
    const int base = (Tn - 32) - t0 + s0;     // in [0, P-63]
    for (int i = tid; i < 1024; i += 256) {
        int r = i >> 4, c = (i & 15) * 4;
        if (r < 63) {
            float4 p4 = *(const float4*)&Pm[(size_t)(base + r) * Dd + h * 64 + c];
            pw[r][c + 0] = f2tf32(p4.x);
            pw[r][c + 1] = f2tf32(p4.y);
            pw[r][c + 2] = f2tf32(p4.z);
            pw[r][c + 3] = f2tf32(p4.w);
        } else {
            pw[r][c + 0] = 0u; pw[r][c + 1] = 0u; pw[r][c + 2] = 0u; pw[r][c + 3] = 0u;
        }
    }
    __syncthreads();

    const int warp = tid >> 5, lane = tid & 31;
    const int g = lane >> 2, t = lane & 3;
    const int mw  = (warp >> 2) * 16;
    const int nwA = (warp & 3) * 8;
    const int nw2 = (warp & 3) * 16;

    float c1r[4] = {};
    float e[2][4] = {};
#pragma unroll
    for (int k0 = 0; k0 < 64; k0 += 8) {
        const int k = k0 + t;
        unsigned a0 = qs[mw + g][k],     a1 = qs[mw + 8 + g][k];
        unsigned a2 = qs[mw + g][k + 4], a3 = qs[mw + 8 + g][k + 4];
        unsigned b0 = kt[nwA + g][k],    b1 = kt[nwA + g][k + 4];
        MMA_TF32(c1r[0], c1r[1], c1r[2], c1r[3], a0, a1, a2, a3, b0, b1);
#pragma unroll
        for (int nt = 0; nt < 2; nt++) {
            int nb = nw2 + nt * 8 + g;
            unsigned p0 = pw[nb][k], p1 = pw[nb][k + 4];
            MMA_TF32(e[nt][0], e[nt][1], e[nt][2], e[nt][3], a0, a1, a2, a3, p0, p1);
        }
    }
    C1[mw + g][nwA + 2 * t]         = c1r[0];
    C1[mw + g][nwA + 2 * t + 1]     = c1r[1];
    C1[mw + 8 + g][nwA + 2 * t]     = c1r[2];
    C1[mw + 8 + g][nwA + 2 * t + 1] = c1r[3];
#pragma unroll
    for (int nt = 0; nt < 2; nt++) {
        int nb = nw2 + nt * 8;
        C2[mw + g][nb + 2 * t]         = e[nt][0];
        C2[mw + g][nb + 2 * t + 1]     = e[nt][1];
        C2[mw + 8 + g][nb + 2 * t]     = e[nt][2];
        C2[mw + 8 + g][nb + 2 * t + 1] = e[nt][3];
    }

    if (tid < 32) {
        float s = 0.f;
#pragma unroll 8
        for (int d = 0; d < 64; d++) s += us[d] * __uint_as_float(kt[tid][d]);
        uk[tid] = s;
    } else if (tid < 96) {
        int r = tid - 32;
        float s = 0.f;
#pragma unroll 8
        for (int d = 0; d < 64; d++) s += vs[d] * __uint_as_float(pw[r][d]);
        vp[r] = s;
    }
    __syncthreads();

    const int tl = tid >> 3, sl = (tid & 7) * 4;
    const int pr = 31 - tl + sl;
    float4 o4;
    o4.x = (C1[tl][sl + 0] + uk[sl + 0] + C2[tl][pr + 0] + vp[pr + 0]) * SCALEf;
    o4.y = (C1[tl][sl + 1] + uk[sl + 1] + C2[tl][pr + 1] + vp[pr + 1]) * SCALEf;
    o4.z = (C1[tl][sl + 2] + uk[sl + 2] + C2[tl][pr + 2] + vp[pr + 2]) * SCALEf;
    o4.w = (C1[tl][sl + 3] + uk[sl + 3] + C2[tl][pr + 3] + vp[pr + 3]) * SCALEf;
    *(float4*)&S[((size_t)z * Tn + (t0 + tl)) * Tn + (s0 + sl)] = o4;
}

// ---------------- row softmax over T=1024: warp-per-row, shuffle-only ----------------
__global__ void __launch_bounds__(256) softmax_kernel(float* __restrict__ S)
{
    const int tid  = threadIdx.x;
    const int warp = tid >> 5, lane = tid & 31;
    const size_t row = (size_t)blockIdx.x * 8 + warp;
    float4* p = (float4*)(S + row * Tn);

    float4 v[8];
    float m = -INFINITY;
#pragma unroll
    for (int j = 0; j < 8; j++) {
        v[j] = p[j * 32 + lane];
        m = fmaxf(m, fmaxf(fmaxf(v[j].x, v[j].y), fmaxf(v[j].z, v[j].w)));
    }
#pragma unroll
    for (int o = 16; o > 0; o >>= 1) m = fmaxf(m, __shfl_xor_sync(0xffffffffu, m, o));
    float s = 0.f;
#pragma unroll
    for (int j = 0; j < 8; j++) {
        v[j].x = expf(v[j].x - m); v[j].y = expf(v[j].y - m);
        v[j].z = expf(v[j].z - m); v[j].w = expf(v[j].w - m);
        s += v[j].x + v[j].y + v[j].z + v[j].w;
    }
#pragma unroll
    for (int o = 16; o > 0; o >>= 1) s += __shfl_xor_sync(0xffffffffu, s, o);
    float inv = 1.0f / s;
#pragma unroll
    for (int j = 0; j < 8; j++) {
        float4 o4;
        o4.x = rnd_tf32(v[j].x * inv); o4.y = rnd_tf32(v[j].y * inv);
        o4.z = rnd_tf32(v[j].z * inv); o4.w = rnd_tf32(v[j].w * inv);
        p[j * 32 + lane] = o4;
    }
}

// =======================================================================
// Fused GLU + depthwise conv (K=31, pad 15) + BN partial stats.
// Grid (Tn/128, Dd/8, Bn), 256 threads = 8 warps; warp w owns channel
// d0+w over a 128-t strip. GLU computed inline from Y2 (B,T,2D); conv
// reads from a per-warp smem window (conflict-free: same row, consecutive
// t); output written to CV2 (B,D,T); per-(block,channel) sum/sumsq
// reduced by shuffle into g_part (deterministic, no atomics).
// =======================================================================
__global__ void __launch_bounds__(256) glu_dwconv(
    const float* __restrict__ Y2, const float* __restrict__ w,
    const float* __restrict__ bias, float* __restrict__ out)
{
    __shared__ float gl[8][158];
    __shared__ float sw[8][31];
    const int t0 = blockIdx.x * 128;
    const int d0 = blockIdx.y * 8;
    const int b  = blockIdx.z;
    const int tid = threadIdx.x;
    const int warp = tid >> 5, lane = tid & 31;

    for (int i = tid; i < 8 * 31; i += 256)
        sw[i / 31][i % 31] = w[(d0 + i / 31) * KWn + i % 31];

    for (int i = tid; i < 8 * 158; i += 256) {
        int dl = i & 7, tt = i >> 3;
        int t = t0 - 15 + tt;
        float v = 0.f;
        if (t >= 0 && t < Tn) {
            size_t base = (size_t)(b * Tn + t) * (2 * Dd) + d0 + dl;
            float a = Y2[base];
            float gg = Y2[base + Dd];
            v = a * sigf(gg);
        }
        gl[dl][tt] = v;
    }
    __syncthreads();

    const int d = d0 + warp;
    const float bz = bias[d];
    float s1 = 0.f, s2 = 0.f;
    float* op = out + ((size_t)b * Dd + d) * Tn + t0;
#pragma unroll
    for (int it = 0; it < 4; it++) {
        int tl = it * 32 + lane;
        float acc = bz;
#pragma unroll
        for (int k = 0; k < KWn; k++) acc += gl[warp][tl + k] * sw[warp][k];
        op[tl] = acc;
        s1 += acc;
        s2 += acc * acc;
    }
#pragma unroll
    for (int o = 16; o > 0; o >>= 1) {
        s1 += __shfl_xor_sync(0xffffffffu, s1, o);
        s2 += __shfl_xor_sync(0xffffffffu, s2, o);
    }
    if (lane == 0) {
        int p = b * 8 + blockIdx.x;     // 32 partial slots
        g_part[p][0][d] = s1;
        g_part[p][1][d] = s2;
    }
}

// ---------------- BN finalize: fold 32 partials into mu/rstd ----------------
__global__ void __launch_bounds__(256) bn_finalize()
{
    int d = blockIdx.x * 256 + threadIdx.x;
    float s1 = 0.f, s2 = 0.f;
#pragma unroll
    for (int p = 0; p < 32; p++) {
        s1 += g_part[p][0][d];
        s2 += g_part[p][1][d];
    }
    float mu = s1 * (1.0f / (Bn * Tn));
    float var = s2 * (1.0f / (Bn * Tn)) - mu * mu;
    g_mu[d] = mu;
    g_rstd[d] = rsqrtf(var + EPSf);
}

// ---------------- BN apply + SiLU + transpose -> (B,T,D), tf32-rounded ----------------
__global__ void __launch_bounds__(256) bn_tr(
    const float* __restrict__ y, const float* __restrict__ g,
    const float* __restrict__ bt, float* __restrict__ out)
{
    __shared__ float tile[32][33];
    const int b = blockIdx.z;
    const int d0 = blockIdx.y * 32, t0 = blockIdx.x * 32;
    const int tid = threadIdx.x;
    const int rr = tid >> 5, cc = tid & 31;
#pragma unroll
    for (int i = 0; i < 4; i++) {
        int dl = rr + i * 8;
        int d = d0 + dl;
        float v = y[((size_t)b * Dd + d) * Tn + t0 + cc];
        v = (v - g_mu[d]) * g_rstd[d] * g[d] + bt[d];
        v = v * sigf(v);
        tile[dl][cc] = rnd_tf32(v);
    }
    __syncthreads();
#pragma unroll
    for (int i = 0; i < 4; i++) {
        int tl = rr + i * 8;
        out[(size_t)(b * Tn + t0 + tl) * Dd + d0 + cc] = tile[cc][tl];
    }
}

// ---------------- copy ----------------
__global__ void __launch_bounds__(256) copy_kernel(const float* __restrict__ in,
                                                   float* __restrict__ out, int n)
{
    int i = blockIdx.x * 256 + threadIdx.x;
    if (i < n) out[i] = in[i];
}

// ---------------- consolidated tf32 rounding / packing prologue ----------------
constexpr int NSEG = 15;
struct RPack {
    const float* src[NSEG];
    float*       dst[NSEG];
    int n[NSEG];
    int cols[NSEG];
    int dstld[NSEG];
};
__global__ void __launch_bounds__(256) round_multi(RPack p)
{
    int sgi = blockIdx.y;
    int i = blockIdx.x * 256 + threadIdx.x;
    if (i >= p.n[sgi]) return;
    int r = i / p.cols[sgi], c = i - r * p.cols[sgi];
    p.dst[sgi][(size_t)r * p.dstld[sgi] + c] = rnd_tf32(p.src[sgi][i]);
}

// ---------------- host-side launch helper ----------------
static void launch_tf32(int mode,
                        const float* A, int lda,
                        const float* W, int ldw,
                        const float* bias, const float* res,
                        float* C, int ldc,
                        int M, int N, int Kd)
{
    dim3 g(N / 64, (M + 127) / 128, 1);
    switch (mode) {
        case 0: tf32gemm<0, 0><<<g, 256, GEMM_SMEM>>>(A, lda, W, ldw, bias, res, C, ldc, M, N, Kd); break;
        case 1: tf32gemm<1, 0><<<g, 256, GEMM_SMEM>>>(A, lda, W, ldw, bias, res, C, ldc, M, N, Kd); break;
        case 2: tf32gemm<2, 0><<<g, 256, GEMM_SMEM>>>(A, lda, W, ldw, bias, res, C, ldc, M, N, Kd); break;
        case 3: tf32gemm<3, 0><<<g, 256, GEMM_SMEM>>>(A, lda, W, ldw, bias, res, C, ldc, M, N, Kd); break;
    }
}

extern "C" void kernel_launch(void* const* d_in, const int* in_sizes, int n_in,
                              void* d_out, int out_size)
{
    const float* in_x   = (const float*)d_in[0];
    const float* pos    = (const float*)d_in[1];
    const float* ln_s   = (const float*)d_in[2];
    const float* ln_b   = (const float*)d_in[3];
    const float* ff1_w1 = (const float*)d_in[4];
    const float* ff1_b1 = (const float*)d_in[5];
    const float* ff1_w2 = (const float*)d_in[6];
    const float* ff1_b2 = (const float*)d_in[7];
    const float* ff2_w1 = (const float*)d_in[8];
    const float* ff2_b1 = (const float*)d_in[9];
    const float* ff2_w2 = (const float*)d_in[10];
    const float* ff2_b2 = (const float*)d_in[11];
    const float* wq     = (const float*)d_in[12];
    const float* bq     = (const float*)d_in[13];
    const float* wk     = (const float*)d_in[14];
    const float* bk     = (const float*)d_in[15];
    const float* wv     = (const float*)d_in[16];
    const float* bv     = (const float*)d_in[17];
    const float* wp     = (const float*)d_in[18];
    const float* wo     = (const float*)d_in[19];
    const float* bo     = (const float*)d_in[20];
    const float* bias_u = (const float*)d_in[21];
    const float* bias_v = (const float*)d_in[22];
    const float* pw1_w  = (const float*)d_in[23];
    const float* pw1_b  = (const float*)d_in[24];
    const float* dw_w   = (const float*)d_in[25];
    const float* dw_b   = (const float*)d_in[26];
    const float* bn_g   = (const float*)d_in[27];
    const float* bn_b   = (const float*)d_in[28];
    const float* pw2_w  = (const float*)d_in[29];
    const float* pw2_b  = (const float*)d_in[30];
    (void)in_sizes; (void)n_in; (void)out_size;

    float *X, *Hb, *FF, *QKV, *Pb, *PosR, *Sb, *CTX, *Y2, *CV2, *WR;
    cudaGetSymbolAddress((void**)&X,    g_X);
    cudaGetSymbolAddress((void**)&Hb,   g_H);
    cudaGetSymbolAddress((void**)&FF,   g_FF);
    cudaGetSymbolAddress((void**)&QKV,  g_QKV);
    cudaGetSymbolAddress((void**)&Pb,   g_P);
    cudaGetSymbolAddress((void**)&PosR, g_PosR);
    cudaGetSymbolAddress((void**)&Sb,   g_S);
    cudaGetSymbolAddress((void**)&CTX,  g_CTX);
    cudaGetSymbolAddress((void**)&Y2,   g_Y2);
    cudaGetSymbolAddress((void**)&CV2,  g_CV2);
    cudaGetSymbolAddress((void**)&WR,   g_WR);

    cudaFuncSetAttribute((const void*)tf32gemm<0, 0>, cudaFuncAttributeMaxDynamicSharedMemorySize, GEMM_SMEM);
    cudaFuncSetAttribute((const void*)tf32gemm<1, 0>, cudaFuncAttributeMaxDynamicSharedMemorySize, GEMM_SMEM);
    cudaFuncSetAttribute((const void*)tf32gemm<2, 0>, cudaFuncAttributeMaxDynamicSharedMemorySize, GEMM_SMEM);
    cudaFuncSetAttribute((const void*)tf32gemm<3, 0>, cudaFuncAttributeMaxDynamicSharedMemorySize, GEMM_SMEM);
    cudaFuncSetAttribute((const void*)tf32gemm<0, 1>, cudaFuncAttributeMaxDynamicSharedMemorySize, GEMM_SMEM);
    cudaFuncSetAttribute((const void*)tf32gemm<0, 2>, cudaFuncAttributeMaxDynamicSharedMemorySize, GEMM_SMEM);

    // consolidated tf32 rounding + QKV weight/bias interleave
    {
        RPack p;
        int i = 0;
        auto seg = [&](const float* s, float* d, size_t n, int cols, int ld) {
            p.src[i] = s; p.dst[i] = d; p.n[i] = (int)n; p.cols[i] = cols; p.dstld[i] = ld; i++;
        };
        seg(ff1_w1, WR + OFF_FF1W1, (size_t)Ln * Dd * DFFd, (int)((size_t)Ln * Dd * DFFd), (int)((size_t)Ln * Dd * DFFd));
        seg(ff1_w2, WR + OFF_FF1W2, (size_t)Ln * DFFd * Dd, (int)((size_t)Ln * DFFd * Dd), (int)((size_t)Ln * DFFd * Dd));
        seg(ff2_w1, WR + OFF_FF2W1, (size_t)Ln * Dd * DFFd, (int)((size_t)Ln * Dd * DFFd), (int)((size_t)Ln * Dd * DFFd));
        seg(ff2_w2, WR + OFF_FF2W2, (size_t)Ln * DFFd * Dd, (int)((size_t)Ln * DFFd * Dd), (int)((size_t)Ln * DFFd * Dd));
        seg(wo,     WR + OFF_WO,    (size_t)Ln * Dd * Dd, (int)((size_t)Ln * Dd * Dd), (int)((size_t)Ln * Dd * Dd));
        seg(wp,     WR + OFF_WP,    (size_t)Ln * Dd * Dd, (int)((size_t)Ln * Dd * Dd), (int)((size_t)Ln * Dd * Dd));
        seg(pw1_w,  WR + OFF_PW1,   (size_t)Ln * Dd * 2 * Dd, (int)((size_t)Ln * Dd * 2 * Dd), (int)((size_t)Ln * Dd * 2 * Dd));
        seg(pw2_w,  WR + OFF_PW2,   (size_t)Ln * Dd * Dd, (int)((size_t)Ln * Dd * Dd), (int)((size_t)Ln * Dd * Dd));
        seg(pos,    PosR,           (size_t)Pn * Dd, (int)((size_t)Pn * Dd), (int)((size_t)Pn * Dd));
        seg(wq, WR + OFF_WQKV + 0,        (size_t)Ln * Dd * Dd, Dd, 3 * Dd);
        seg(wk, WR + OFF_WQKV + Dd,       (size_t)Ln * Dd * Dd, Dd, 3 * Dd);
        seg(wv, WR + OFF_WQKV + 2 * Dd,   (size_t)Ln * Dd * Dd, Dd, 3 * Dd);
        seg(bq, WR + OFF_BQKV + 0,        (size_t)Ln * Dd, Dd, 3 * Dd);
        seg(bk, WR + OFF_BQKV + Dd,       (size_t)Ln * Dd, Dd, 3 * Dd);
        seg(bv, WR + OFF_BQKV + 2 * Dd,   (size_t)Ln * Dd, Dd, 3 * Dd);
        round_multi<<<dim3(((size_t)Ln * Dd * DFFd + 255) / 256, NSEG), 256>>>(p);
    }

    copy_kernel<<<(BTn * Dd) / 256, 256>>>(in_x, X, BTn * Dd);

    // pos projections for BOTH layers, hoisted + batched
    tf32gemm<0, 2><<<dim3(Dd / 64, (Pn + 127) / 128, Ln), 256, GEMM_SMEM>>>(
        PosR, Dd, WR + OFF_WP, Dd, nullptr, nullptr, Pb, Dd, Pn, Dd, Dd);

    for (int l = 0; l < Ln; ++l) {
        const float* lnS = ln_s + (size_t)l * 5 * Dd;
        const float* lnB = ln_b + (size_t)l * 5 * Dd;

        // ---- macaron FFN 1 (half residual) ----
        ln_kernel<true><<<BTn, 128>>>(X, lnS, lnB, Hb);
        launch_tf32(1, Hb, Dd, WR + OFF_FF1W1 + (size_t)l * Dd * DFFd, DFFd,
                    ff1_b1 + (size_t)l * DFFd, nullptr, FF, DFFd, BTn, DFFd, Dd);
        launch_tf32(3, FF, DFFd, WR + OFF_FF1W2 + (size_t)l * DFFd * Dd, Dd,
                    ff1_b2 + (size_t)l * Dd, X, X, Dd, BTn, Dd, DFFd);

        // ---- rel-pos MHSA ----
        ln_kernel<true><<<BTn, 128>>>(X, lnS + Dd, lnB + Dd, Hb);
        launch_tf32(0, Hb, Dd, WR + OFF_WQKV + (size_t)l * Dd * 3 * Dd, 3 * Dd,
                    WR + OFF_BQKV + (size_t)l * 3 * Dd, nullptr, QKV, 3 * Dd, BTn, 3 * Dd, Dd);

        attn_scores<<<dim3(Tn / 32, Tn / 32, Bn * Hn), 256>>>(
            QKV, 3 * Dd, QKV + Dd, 3 * Dd, Pb + (size_t)l * Pn * Dd,
            bias_u + (size_t)l * Hn * DKn, bias_v + (size_t)l * Hn * DKn, Sb);
        softmax_kernel<<<Bn * Hn * Tn / 8, 256>>>(Sb);

        tf32gemm<0, 1><<<dim3(1, Tn / 128, Bn * Hn), 256, GEMM_SMEM>>>(
            Sb, Tn, QKV + 2 * Dd, 3 * Dd, nullptr, nullptr, CTX, Dd, Tn, DKn, Tn);

        launch_tf32(2, CTX, Dd, WR + OFF_WO + (size_t)l * Dd * Dd, Dd,
                    bo + (size_t)l * Dd, X, X, Dd, BTn, Dd, Dd);

        // ---- conv module (fused GLU+dwconv+BN-stats) ----
        ln_kernel<true><<<BTn, 128>>>(X, lnS + 2 * Dd, lnB + 2 * Dd, Hb);
        launch_tf32(0, Hb, Dd, WR + OFF_PW1 + (size_t)l * Dd * 2 * Dd, 2 * Dd,
                    pw1_b + (size_t)l * 2 * Dd, nullptr, Y2, 2 * Dd, BTn, 2 * Dd, Dd);
        glu_dwconv<<<dim3(Tn / 128, Dd / 8, Bn), 256>>>(
            Y2, dw_w + (size_t)l * Dd * KWn, dw_b + (size_t)l * Dd, CV2);
        bn_finalize<<<Dd / 256, 256>>>();
        bn_tr<<<dim3(Tn / 32, Dd / 32, Bn), 256>>>(
            CV2, bn_g + (size_t)l * Dd, bn_b + (size_t)l * Dd, Hb);
        launch_tf32(2, Hb, Dd, WR + OFF_PW2 + (size_t)l * Dd * Dd, Dd,
                    pw2_b + (size_t)l * Dd, X, X, Dd, BTn, Dd, Dd);

        // ---- macaron FFN 2 (half residual) ----
        ln_kernel<true><<<BTn, 128>>>(X, lnS + 3 * Dd, lnB + 3 * Dd, Hb);
        launch_tf32(1, Hb, Dd, WR + OFF_FF2W1 + (size_t)l * Dd * DFFd, DFFd,
                    ff2_b1 + (size_t)l * DFFd, nullptr, FF, DFFd, BTn, DFFd, Dd);
        launch_tf32(3, FF, DFFd, WR + OFF_FF2W2 + (size_t)l * DFFd * Dd, Dd,
                    ff2_b2 + (size_t)l * Dd, X, X, Dd, BTn, Dd, DFFd);

        // ---- final per-layer LN (full precision) ----
        float* outp = (l == Ln - 1) ? (float*)d_out : X;
        ln_kernel<false><<<BTn, 128>>>(X, lnS + 4 * Dd, lnB + 4 * Dd, outp);
    }
}

// round 16
// speedup vs baseline: 1.0481x; 1.0019x over previous
#include <cuda_runtime.h>
#include <math.h>

// ---------------- problem constants ----------------
constexpr int Dd   = 512;
constexpr int Hn   = 8;
constexpr int DFFd = 2048;
constexpr int KWn  = 31;
constexpr int Ln   = 2;
constexpr int Bn   = 4;
constexpr int Tn   = 1024;
constexpr int DKn  = 64;
constexpr int Pn   = 2 * Tn - 1;      // 2047
constexpr int BTn  = Bn * Tn;         // 4096
constexpr float EPSf   = 1e-5f;
constexpr float SCALEf = 0.125f;      // 1/sqrt(64)

// rounded-weight scratch layout (floats)
constexpr size_t OFF_FF1W1 = 0;
constexpr size_t OFF_FF1W2 = OFF_FF1W1 + (size_t)Ln * Dd * DFFd;
constexpr size_t OFF_FF2W1 = OFF_FF1W2 + (size_t)Ln * DFFd * Dd;
constexpr size_t OFF_FF2W2 = OFF_FF2W1 + (size_t)Ln * Dd * DFFd;
constexpr size_t OFF_WQKV  = OFF_FF2W2 + (size_t)Ln * DFFd * Dd;   // [Ln][512][1536]
constexpr size_t OFF_WO    = OFF_WQKV + (size_t)Ln * Dd * 3 * Dd;
constexpr size_t OFF_WP    = OFF_WO + (size_t)Ln * Dd * Dd;
constexpr size_t OFF_PW1   = OFF_WP + (size_t)Ln * Dd * Dd;
constexpr size_t OFF_PW2   = OFF_PW1 + (size_t)Ln * Dd * 2 * Dd;
constexpr size_t OFF_BQKV  = OFF_PW2 + (size_t)Ln * Dd * Dd;       // [Ln][1536]
constexpr size_t WR_TOTAL  = OFF_BQKV + (size_t)Ln * 3 * Dd;

// GEMM dynamic smem: 3 stages x (A 128x32 + B 32x64) u32
constexpr int GEMM_STAGE_U32 = 128 * 32 + 32 * 64;     // 6144
constexpr int GEMM_SMEM = 3 * GEMM_STAGE_U32 * 4;      // 73728 B

// ---------------- device scratch (allocation-free) ----------------
__device__ float g_X  [BTn * Dd];
__device__ float g_H  [BTn * Dd];
__device__ float g_FF [BTn * DFFd];
__device__ float g_QKV[(size_t)BTn * 3 * Dd];
__device__ float g_P  [(size_t)Ln * Pn * Dd];   // per-layer pos projections
__device__ float g_PosR[Pn * Dd];               // tf32-rounded pos
__device__ float g_S  [(size_t)Bn * Hn * Tn * Tn];  // 128 MB scores
__device__ float g_CTX[BTn * Dd];
__device__ float g_Y2 [BTn * 2 * Dd];
__device__ float g_CV2[Bn * Dd * Tn];
__device__ float g_part[32][2][Dd];             // BN partials: [b*8+tblk][sum|sq][d]
__device__ float g_WR [WR_TOTAL];          // tf32-rounded weights

__device__ __forceinline__ float sigf(float x) { return 1.0f / (1.0f + __expf(-x)); }

__device__ __forceinline__ unsigned f2tf32(float x) {
    unsigned u;
    asm("cvt.rna.tf32.f32 %0, %1;" : "=r"(u) : "f"(x));
    return u;
}
__device__ __forceinline__ float rnd_tf32(float x) { return __uint_as_float(f2tf32(x)); }

#define MMA_TF32(c0,c1,c2,c3,a0,a1,a2,a3,b0,b1)                              \
    asm volatile(                                                            \
        "mma.sync.aligned.m16n8k8.row.col.f32.tf32.tf32.f32 "                \
        "{%0,%1,%2,%3},{%4,%5,%6,%7},{%8,%9},{%0,%1,%2,%3};"                 \
        : "+f"(c0), "+f"(c1), "+f"(c2), "+f"(c3)                             \
        : "r"(a0), "r"(a1), "r"(a2), "r"(a3), "r"(b0), "r"(b1))

__device__ __forceinline__ void cpa16(unsigned dst, const void* src, int szbytes) {
    asm volatile("cp.async.cg.shared.global [%0], [%1], 16, %2;"
                 :: "r"(dst), "l"(src), "r"(szbytes));
}

// =======================================================================
// TF32 tensor-core GEMM, cp.async 3-stage pipeline, XOR-swizzled dyn smem.
// C = epilogue(A (MxK, lda) @ W (KxN, ldw) + bias)
// Tile: BM=128, BN=64, BK=32. 256 threads = 8 warps (4x2), warp 32x32.
// Inputs MUST be tf32-pre-rounded floats.
// MODE: 0 = (+bias, rnd), 1 = silu(+bias, rnd), 2 = res + (.), 3 = res + 0.5*(.)
// BMODE: 0 = plain; 1 = AV batch (z -> b,h of S@V); 2 = weight batch (pos proj).
// =======================================================================
template <int MODE, int BMODE>
__global__ void __launch_bounds__(256) tf32gemm(
    const float* __restrict__ A, int lda,
    const float* __restrict__ W, int ldw,
    const float* __restrict__ bias,
    const float* __restrict__ res,
    float* __restrict__ C, int ldc,
    int M, int N, int Kd)
{
    extern __shared__ unsigned gsm[];

    if (BMODE == 1) {
        int z = blockIdx.z;                       // z = b*8 + h
        A += (size_t)z * Tn * Tn;                 // S[b][h] (T x T)
        W += (size_t)(z >> 3) * Tn * ldw + (size_t)(z & 7) * DKn;
        C += (size_t)(z >> 3) * Tn * ldc + (size_t)(z & 7) * DKn;
    } else if (BMODE == 2) {
        int z = blockIdx.z;                       // layer index
        W += (size_t)z * Dd * ldw;
        C += (size_t)z * Pn * ldc;
    }

    const int bm = blockIdx.y * 128, bn = blockIdx.x * 64;
    const int tid  = threadIdx.x;
    const int warp = tid >> 5, lane = tid & 31;
    const int g = lane >> 2, t = lane & 3;
    const int wm = (warp >> 1) * 32, wn = (warp & 1) * 32;

    unsigned smBase = (unsigned)__cvta_generic_to_shared(gsm);

    auto loadTile = [&](int stage, int k0) {
        unsigned aOff = (unsigned)stage * GEMM_STAGE_U32;
#pragma unroll
        for (int i = 0; i < 4; i++) {
            int lin = i * 256 + tid;
            int row = lin >> 3, ck = lin & 7;
            int pc = ck ^ (row & 7);
            unsigned dst = smBase + (aOff + row * 32 + pc * 4) * 4;
            const float* src = A + (size_t)(bm + row) * lda + k0 + ck * 4;
            cpa16(dst, src, (bm + row < M) ? 16 : 0);
        }
        unsigned bOff = aOff + 4096;
#pragma unroll
        for (int i = 0; i < 2; i++) {
            int lin = i * 256 + tid;
            int kr = lin >> 4, c4 = lin & 15;
            int pc = c4 ^ (2 * (kr & 3));
            unsigned dst = smBase + (bOff + kr * 64 + pc * 4) * 4;
            const float* src = W + (size_t)(k0 + kr) * ldw + bn + c4 * 4;
            cpa16(dst, src, 16);
        }
        asm volatile("cp.async.commit_group;");
    };

    float acc[2][4][4] = {};

    int colB[4];
#pragma unroll
    for (int nt = 0; nt < 4; nt++) {
        int nb = wn + nt * 8 + g;
        colB[nt] = (((nb >> 2) ^ (2 * t)) << 2) | (nb & 3);
    }
    const int rA0 = wm + g, rA1 = wm + 16 + g;

    const int nk = Kd >> 5;
    loadTile(0, 0);
    loadTile(1, 32);

    for (int kb = 0; kb < nk; kb++) {
        if (kb + 2 < nk) {
            asm volatile("cp.async.wait_group 1;");
        } else {
            asm volatile("cp.async.wait_group 0;");
        }
        __syncthreads();

        const unsigned* Ac = gsm + (kb % 3) * GEMM_STAGE_U32;
        const unsigned* Bc = Ac + 4096;
#pragma unroll
        for (int kt = 0; kt < 4; kt++) {
            const int c0 = (((2 * kt) ^ g) << 2) | t;
            const int c1 = (((2 * kt + 1) ^ g) << 2) | t;
            const int kr = kt * 8 + t;
            unsigned a[2][4];
            a[0][0] = Ac[rA0 * 32 + c0];       a[0][1] = Ac[(rA0 + 8) * 32 + c0];
            a[0][2] = Ac[rA0 * 32 + c1];       a[0][3] = Ac[(rA0 + 8) * 32 + c1];
            a[1][0] = Ac[rA1 * 32 + c0];       a[1][1] = Ac[(rA1 + 8) * 32 + c0];
            a[1][2] = Ac[rA1 * 32 + c1];       a[1][3] = Ac[(rA1 + 8) * 32 + c1];
            unsigned b[4][2];
#pragma unroll
            for (int nt = 0; nt < 4; nt++) {
                b[nt][0] = Bc[kr * 64 + colB[nt]];
                b[nt][1] = Bc[(kr + 4) * 64 + colB[nt]];
            }
#pragma unroll
            for (int mt = 0; mt < 2; mt++)
#pragma unroll
                for (int nt = 0; nt < 4; nt++)
                    MMA_TF32(acc[mt][nt][0], acc[mt][nt][1], acc[mt][nt][2], acc[mt][nt][3],
                             a[mt][0], a[mt][1], a[mt][2], a[mt][3],
                             b[nt][0], b[nt][1]);
        }
        if (kb + 2 < nk) loadTile((kb + 2) % 3, (kb + 2) * 32);
    }

#pragma unroll
    for (int mt = 0; mt < 2; mt++) {
        int r0 = bm + wm + mt * 16 + g;
        int r1 = r0 + 8;
#pragma unroll
        for (int nt = 0; nt < 4; nt++) {
            int col = bn + wn + nt * 8 + 2 * t;
#pragma unroll
            for (int half = 0; half < 2; half++) {
                int row = half ? r1 : r0;
                if (row >= M) continue;
                float v0 = acc[mt][nt][half * 2 + 0];
                float v1 = acc[mt][nt][half * 2 + 1];
                if (bias) { v0 += bias[col]; v1 += bias[col + 1]; }
                if (MODE == 1) { v0 = v0 * sigf(v0); v1 = v1 * sigf(v1); }
                if (MODE == 0 || MODE == 1) { v0 = rnd_tf32(v0); v1 = rnd_tf32(v1); }
                if (MODE == 2) {
                    v0 = res[(size_t)row * ldc + col] + v0;
                    v1 = res[(size_t)row * ldc + col + 1] + v1;
                }
                if (MODE == 3) {
                    v0 = res[(size_t)row * ldc + col] + 0.5f * v0;
                    v1 = res[(size_t)row * ldc + col + 1] + 0.5f * v1;
                }
                *(float2*)&C[(size_t)row * ldc + col] = make_float2(v0, v1);
            }
        }
    }
}

// ---------------- LayerNorm: 128 threads, float4, warp shuffles ----------------
template <bool RND>
__global__ void __launch_bounds__(128) ln_kernel(
    const float* __restrict__ x, const float* __restrict__ s,
    const float* __restrict__ b, float* __restrict__ out)
{
    __shared__ float red[8];
    const int row = blockIdx.x;
    const int tid = threadIdx.x;
    const int lane = tid & 31, wid = tid >> 5;
    float4 v = ((const float4*)(x + (size_t)row * Dd))[tid];

    float s1 = v.x + v.y + v.z + v.w;
#pragma unroll
    for (int o = 16; o > 0; o >>= 1) s1 += __shfl_xor_sync(0xffffffffu, s1, o);
    if (lane == 0) red[wid] = s1;
    __syncthreads();
    float mean = (red[0] + red[1] + red[2] + red[3]) * (1.0f / Dd);

    float4 d;
    d.x = v.x - mean; d.y = v.y - mean; d.z = v.z - mean; d.w = v.w - mean;
    float s2 = d.x * d.x + d.y * d.y + d.z * d.z + d.w * d.w;
#pragma unroll
    for (int o = 16; o > 0; o >>= 1) s2 += __shfl_xor_sync(0xffffffffu, s2, o);
    if (lane == 0) red[4 + wid] = s2;
    __syncthreads();
    float rstd = rsqrtf((red[4] + red[5] + red[6] + red[7]) * (1.0f / Dd) + EPSf);

    float4 sc = ((const float4*)s)[tid];
    float4 bc = ((const float4*)b)[tid];
    float4 o4;
    o4.x = d.x * rstd * sc.x + bc.x;
    o4.y = d.y * rstd * sc.y + bc.y;
    o4.z = d.z * rstd * sc.z + bc.z;
    o4.w = d.w * rstd * sc.w + bc.w;
    if (RND) {
        o4.x = rnd_tf32(o4.x); o4.y = rnd_tf32(o4.y);
        o4.z = rnd_tf32(o4.z); o4.w = rnd_tf32(o4.w);
    }
    ((float4*)(out + (size_t)row * Dd))[tid] = o4;
}

// =======================================================================
// rel-pos attention scores on tensor cores (R8-verified).
// S[b,h,t,s] = ((q+u)·k[s] + (q+v)·p[T-1-t+s]) * SCALE
// =======================================================================
__global__ void __launch_bounds__(256) attn_scores(
    const float* __restrict__ Q, int ldq,
    const float* __restrict__ Km, int ldk,
    const float* __restrict__ Pm,
    const float* __restrict__ bu, const float* __restrict__ bvv,
    float* __restrict__ S)
{
    __shared__ unsigned qs[32][66], kt[32][66], pw[64][66];
    __shared__ float C1[32][33];
    __shared__ float C2[32][68];
    __shared__ float uk[32], vp[64];
    __shared__ float us[64], vs[64];

    const int z = blockIdx.z;
    const int b = z >> 3, h = z & 7;
    const int t0 = blockIdx.y << 5, s0 = blockIdx.x << 5;
    const int tid = threadIdx.x;

    if (tid < 16)
        ((float4*)us)[tid] = ((const float4*)(bu + h * 64))[tid];
    else if (tid < 32)
        ((float4*)vs)[tid - 16] = ((const float4*)(bvv + h * 64))[tid - 16];

    for (int i = tid; i < 512; i += 256) {
        int r = i >> 4, c = (i & 15) * 4;
        float4 q4 = *(const float4*)&Q[(size_t)(b * Tn + t0 + r) * ldq + h * 64 + c];
        qs[r][c + 0] = f2tf32(q4.x);
        qs[r][c + 1] = f2tf32(q4.y);
        qs[r][c + 2] = f2tf32(q4.z);
        qs[r][c + 3] = f2tf32(q4.w);
        float4 k4 = *(const float4*)&Km[(size_t)(b * Tn + s0 + r) * ldk + h * 64 + c];
        kt[r][c + 0] = f2tf32(k4.x);
        kt[r][c + 1] = f2tf32(k4.y);
        kt[r][c + 2] = f2tf32(k4.z);
        kt[r][c + 3] = f2tf32(k4.w);
    }
    const int base = (Tn - 32) - t0 + s0;     // in [0, P-63]
    for (int i = tid; i < 1024; i += 256) {
        int r = i >> 4, c = (i & 15) * 4;
        if (r < 63) {
            float4 p4 = *(const float4*)&Pm[(size_t)(base + r) * Dd + h * 64 + c];
            pw[r][c + 0] = f2tf32(p4.x);
            pw[r][c + 1] = f2tf32(p4.y);
            pw[r][c + 2] = f2tf32(p4.z);
            pw[r][c + 3] = f2tf32(p4.w);
        } else {
            pw[r][c + 0] = 0u; pw[r][c + 1] = 0u; pw[r][c + 2] = 0u; pw[r][c + 3] = 0u;
        }
    }
    __syncthreads();

    const int warp = tid >> 5, lane = tid & 31;
    const int g = lane >> 2, t = lane & 3;
    const int mw  = (warp >> 2) * 16;
    const int nwA = (warp & 3) * 8;
    const int nw2 = (warp & 3) * 16;

    float c1r[4] = {};
    float e[2][4] = {};
#pragma unroll
    for (int k0 = 0; k0 < 64; k0 += 8) {
        const int k = k0 + t;
        unsigned a0 = qs[mw + g][k],     a1 = qs[mw + 8 + g][k];
        unsigned a2 = qs[mw + g][k + 4], a3 = qs[mw + 8 + g][k + 4];
        unsigned b0 = kt[nwA + g][k],    b1 = kt[nwA + g][k + 4];
        MMA_TF32(c1r[0], c1r[1], c1r[2], c1r[3], a0, a1, a2, a3, b0, b1);
#pragma unroll
        for (int nt = 0; nt < 2; nt++) {
            int nb = nw2 + nt * 8 + g;
            unsigned p0 = pw[nb][k], p1 = pw[nb][k + 4];
            MMA_TF32(e[nt][0], e[nt][1], e[nt][2], e[nt][3], a0, a1, a2, a3, p0, p1);
        }
    }
    C1[mw + g][nwA + 2 * t]         = c1r[0];
    C1[mw + g][nwA + 2 * t + 1]     = c1r[1];
    C1[mw + 8 + g][nwA + 2 * t]     = c1r[2];
    C1[mw + 8 + g][nwA + 2 * t + 1] = c1r[3];
#pragma unroll
    for (int nt = 0; nt < 2; nt++) {
        int nb = nw2 + nt * 8;
        C2[mw + g][nb + 2 * t]         = e[nt][0];
        C2[mw + g][nb + 2 * t + 1]     = e[nt][1];
        C2[mw + 8 + g][nb + 2 * t]     = e[nt][2];
        C2[mw + 8 + g][nb + 2 * t + 1] = e[nt][3];
    }

    if (tid < 32) {
        float s = 0.f;
#pragma unroll 8
        for (int d = 0; d < 64; d++) s += us[d] * __uint_as_float(kt[tid][d]);
        uk[tid] = s;
    } else if (tid < 96) {
        int r = tid - 32;
        float s = 0.f;
#pragma unroll 8
        for (int d = 0; d < 64; d++) s += vs[d] * __uint_as_float(pw[r][d]);
        vp[r] = s;
    }
    __syncthreads();

    const int tl = tid >> 3, sl = (tid & 7) * 4;
    const int pr = 31 - tl + sl;
    float4 o4;
    o4.x = (C1[tl][sl + 0] + uk[sl + 0] + C2[tl][pr + 0] + vp[pr + 0]) * SCALEf;
    o4.y = (C1[tl][sl + 1] + uk[sl + 1] + C2[tl][pr + 1] + vp[pr + 1]) * SCALEf;
    o4.z = (C1[tl][sl + 2] + uk[sl + 2] + C2[tl][pr + 2] + vp[pr + 2]) * SCALEf;
    o4.w = (C1[tl][sl + 3] + uk[sl + 3] + C2[tl][pr + 3] + vp[pr + 3]) * SCALEf;
    *(float4*)&S[((size_t)z * Tn + (t0 + tl)) * Tn + (s0 + sl)] = o4;
}

// ---------------- row softmax over T=1024: warp-per-row, shuffle-only ----------------
__global__ void __launch_bounds__(256) softmax_kernel(float* __restrict__ S)
{
    const int tid  = threadIdx.x;
    const int warp = tid >> 5, lane = tid & 31;
    const size_t row = (size_t)blockIdx.x * 8 + warp;
    float4* p = (float4*)(S + row * Tn);

    float4 v[8];
    float m = -INFINITY;
#pragma unroll
    for (int j = 0; j < 8; j++) {
        v[j] = p[j * 32 + lane];
        m = fmaxf(m, fmaxf(fmaxf(v[j].x, v[j].y), fmaxf(v[j].z, v[j].w)));
    }
#pragma unroll
    for (int o = 16; o > 0; o >>= 1) m = fmaxf(m, __shfl_xor_sync(0xffffffffu, m, o));
    float s = 0.f;
#pragma unroll
    for (int j = 0; j < 8; j++) {
        v[j].x = __expf(v[j].x - m); v[j].y = __expf(v[j].y - m);
        v[j].z = __expf(v[j].z - m); v[j].w = __expf(v[j].w - m);
        s += v[j].x + v[j].y + v[j].z + v[j].w;
    }
#pragma unroll
    for (int o = 16; o > 0; o >>= 1) s += __shfl_xor_sync(0xffffffffu, s, o);
    float inv = 1.0f / s;
#pragma unroll
    for (int j = 0; j < 8; j++) {
        float4 o4;
        o4.x = rnd_tf32(v[j].x * inv); o4.y = rnd_tf32(v[j].y * inv);
        o4.z = rnd_tf32(v[j].z * inv); o4.w = rnd_tf32(v[j].w * inv);
        p[j * 32 + lane] = o4;
    }
}

// =======================================================================
// Fused GLU + depthwise conv (K=31, pad 15) + BN partial stats.
// =======================================================================
__global__ void __launch_bounds__(256) glu_dwconv(
    const float* __restrict__ Y2, const float* __restrict__ w,
    const float* __restrict__ bias, float* __restrict__ out)
{
    __shared__ float gl[8][158];
    __shared__ float sw[8][31];
    const int t0 = blockIdx.x * 128;
    const int d0 = blockIdx.y * 8;
    const int b  = blockIdx.z;
    const int tid = threadIdx.x;
    const int warp = tid >> 5, lane = tid & 31;

    for (int i = tid; i < 8 * 31; i += 256)
        sw[i / 31][i % 31] = w[(d0 + i / 31) * KWn + i % 31];

    for (int i = tid; i < 8 * 158; i += 256) {
        int dl = i & 7, tt = i >> 3;
        int t = t0 - 15 + tt;
        float v = 0.f;
        if (t >= 0 && t < Tn) {
            size_t base = (size_t)(b * Tn + t) * (2 * Dd) + d0 + dl;
            float a = Y2[base];
            float gg = Y2[base + Dd];
            v = a * sigf(gg);
        }
        gl[dl][tt] = v;
    }
    __syncthreads();

    const int d = d0 + warp;
    const float bz = bias[d];
    float s1 = 0.f, s2 = 0.f;
    float* op = out + ((size_t)b * Dd + d) * Tn + t0;
#pragma unroll
    for (int it = 0; it < 4; it++) {
        int tl = it * 32 + lane;
        float acc = bz;
#pragma unroll
        for (int k = 0; k < KWn; k++) acc += gl[warp][tl + k] * sw[warp][k];
        op[tl] = acc;
        s1 += acc;
        s2 += acc * acc;
    }
#pragma unroll
    for (int o = 16; o > 0; o >>= 1) {
        s1 += __shfl_xor_sync(0xffffffffu, s1, o);
        s2 += __shfl_xor_sync(0xffffffffu, s2, o);
    }
    if (lane == 0) {
        int p = b * 8 + blockIdx.x;     // 32 partial slots
        g_part[p][0][d] = s1;
        g_part[p][1][d] = s2;
    }
}

// ---------------- BN apply + SiLU + transpose -> (B,T,D), tf32-rounded ----------------
// Folds the 32 BN partials per channel in-block (deterministic order,
// identical summation to the old bn_finalize); removes that launch.
__global__ void __launch_bounds__(256) bn_tr(
    const float* __restrict__ y, const float* __restrict__ g,
    const float* __restrict__ bt, float* __restrict__ out)
{
    __shared__ float tile[32][33];
    __shared__ float mu_s[32], rs_s[32];
    const int b = blockIdx.z;
    const int d0 = blockIdx.y * 32, t0 = blockIdx.x * 32;
    const int tid = threadIdx.x;
    const int rr = tid >> 5, cc = tid & 31;

    if (tid < 32) {
        int d = d0 + tid;
        float s1 = 0.f, s2 = 0.f;
#pragma unroll
        for (int p = 0; p < 32; p++) {
            s1 += g_part[p][0][d];
            s2 += g_part[p][1][d];
        }
        float mu = s1 * (1.0f / (Bn * Tn));
        float var = s2 * (1.0f / (Bn * Tn)) - mu * mu;
        mu_s[tid] = mu;
        rs_s[tid] = rsqrtf(var + EPSf);
    }
    __syncthreads();

#pragma unroll
    for (int i = 0; i < 4; i++) {
        int dl = rr + i * 8;
        int d = d0 + dl;
        float v = y[((size_t)b * Dd + d) * Tn + t0 + cc];
        v = (v - mu_s[dl]) * rs_s[dl] * g[d] + bt[d];
        v = v * sigf(v);
        tile[dl][cc] = rnd_tf32(v);
    }
    __syncthreads();
#pragma unroll
    for (int i = 0; i < 4; i++) {
        int tl = rr + i * 8;
        out[(size_t)(b * Tn + t0 + tl) * Dd + d0 + cc] = tile[cc][tl];
    }
}

// ---------------- copy ----------------
__global__ void __launch_bounds__(256) copy_kernel(const float* __restrict__ in,
                                                   float* __restrict__ out, int n)
{
    int i = blockIdx.x * 256 + threadIdx.x;
    if (i < n) out[i] = in[i];
}

// ---------------- consolidated tf32 rounding / packing prologue ----------------
constexpr int NSEG = 15;
struct RPack {
    const float* src[NSEG];
    float*       dst[NSEG];
    int n[NSEG];
    int cols[NSEG];
    int dstld[NSEG];
};
__global__ void __launch_bounds__(256) round_multi(RPack p)
{
    int sgi = blockIdx.y;
    int i = blockIdx.x * 256 + threadIdx.x;
    if (i >= p.n[sgi]) return;
    int r = i / p.cols[sgi], c = i - r * p.cols[sgi];
    p.dst[sgi][(size_t)r * p.dstld[sgi] + c] = rnd_tf32(p.src[sgi][i]);
}

// ---------------- host-side launch helper ----------------
static void launch_tf32(int mode,
                        const float* A, int lda,
                        const float* W, int ldw,
                        const float* bias, const float* res,
                        float* C, int ldc,
                        int M, int N, int Kd)
{
    dim3 g(N / 64, (M + 127) / 128, 1);
    switch (mode) {
        case 0: tf32gemm<0, 0><<<g, 256, GEMM_SMEM>>>(A, lda, W, ldw, bias, res, C, ldc, M, N, Kd); break;
        case 1: tf32gemm<1, 0><<<g, 256, GEMM_SMEM>>>(A, lda, W, ldw, bias, res, C, ldc, M, N, Kd); break;
        case 2: tf32gemm<2, 0><<<g, 256, GEMM_SMEM>>>(A, lda, W, ldw, bias, res, C, ldc, M, N, Kd); break;
        case 3: tf32gemm<3, 0><<<g, 256, GEMM_SMEM>>>(A, lda, W, ldw, bias, res, C, ldc, M, N, Kd); break;
    }
}

extern "C" void kernel_launch(void* const* d_in, const int* in_sizes, int n_in,
                              void* d_out, int out_size)
{
    const float* in_x   = (const float*)d_in[0];
    const float* pos    = (const float*)d_in[1];
    const float* ln_s   = (const float*)d_in[2];
    const float* ln_b   = (const float*)d_in[3];
    const float* ff1_w1 = (const float*)d_in[4];
    const float* ff1_b1 = (const float*)d_in[5];
    const float* ff1_w2 = (const float*)d_in[6];
    const float* ff1_b2 = (const float*)d_in[7];
    const float* ff2_w1 = (const float*)d_in[8];
    const float* ff2_b1 = (const float*)d_in[9];
    const float* ff2_w2 = (const float*)d_in[10];
    const float* ff2_b2 = (const float*)d_in[11];
    const float* wq     = (const float*)d_in[12];
    const float* bq     = (const float*)d_in[13];
    const float* wk     = (const float*)d_in[14];
    const float* bk     = (const float*)d_in[15];
    const float* wv     = (const float*)d_in[16];
    const float* bv     = (const float*)d_in[17];
    const float* wp     = (const float*)d_in[18];
    const float* wo     = (const float*)d_in[19];
    const float* bo     = (const float*)d_in[20];
    const float* bias_u = (const float*)d_in[21];
    const float* bias_v = (const float*)d_in[22];
    const float* pw1_w  = (const float*)d_in[23];
    const float* pw1_b  = (const float*)d_in[24];
    const float* dw_w   = (const float*)d_in[25];
    const float* dw_b   = (const float*)d_in[26];
    const float* bn_g   = (const float*)d_in[27];
    const float* bn_b   = (const float*)d_in[28];
    const float* pw2_w  = (const float*)d_in[29];
    const float* pw2_b  = (const float*)d_in[30];
    (void)in_sizes; (void)n_in; (void)out_size;

    float *X, *Hb, *FF, *QKV, *Pb, *PosR, *Sb, *CTX, *Y2, *CV2, *WR;
    cudaGetSymbolAddress((void**)&X,    g_X);
    cudaGetSymbolAddress((void**)&Hb,   g_H);
    cudaGetSymbolAddress((void**)&FF,   g_FF);
    cudaGetSymbolAddress((void**)&QKV,  g_QKV);
    cudaGetSymbolAddress((void**)&Pb,   g_P);
    cudaGetSymbolAddress((void**)&PosR, g_PosR);
    cudaGetSymbolAddress((void**)&Sb,   g_S);
    cudaGetSymbolAddress((void**)&CTX,  g_CTX);
    cudaGetSymbolAddress((void**)&Y2,   g_Y2);
    cudaGetSymbolAddress((void**)&CV2,  g_CV2);
    cudaGetSymbolAddress((void**)&WR,   g_WR);

    cudaFuncSetAttribute((const void*)tf32gemm<0, 0>, cudaFuncAttributeMaxDynamicSharedMemorySize, GEMM_SMEM);
    cudaFuncSetAttribute((const void*)tf32gemm<1, 0>, cudaFuncAttributeMaxDynamicSharedMemorySize, GEMM_SMEM);
    cudaFuncSetAttribute((const void*)tf32gemm<2, 0>, cudaFuncAttributeMaxDynamicSharedMemorySize, GEMM_SMEM);
    cudaFuncSetAttribute((const void*)tf32gemm<3, 0>, cudaFuncAttributeMaxDynamicSharedMemorySize, GEMM_SMEM);
    cudaFuncSetAttribute((const void*)tf32gemm<0, 1>, cudaFuncAttributeMaxDynamicSharedMemorySize, GEMM_SMEM);
    cudaFuncSetAttribute((const void*)tf32gemm<0, 2>, cudaFuncAttributeMaxDynamicSharedMemorySize, GEMM_SMEM);

    // consolidated tf32 rounding + QKV weight/bias interleave
    {
        RPack p;
        int i = 0;
        auto seg = [&](const float* s, float* d, size_t n, int cols, int ld) {
            p.src[i] = s; p.dst[i] = d; p.n[i] = (int)n; p.cols[i] = cols; p.dstld[i] = ld; i++;
        };
        seg(ff1_w1, WR + OFF_FF1W1, (size_t)Ln * Dd * DFFd, (int)((size_t)Ln * Dd * DFFd), (int)((size_t)Ln * Dd * DFFd));
        seg(ff1_w2, WR + OFF_FF1W2, (size_t)Ln * DFFd * Dd, (int)((size_t)Ln * DFFd * Dd), (int)((size_t)Ln * DFFd * Dd));
        seg(ff2_w1, WR + OFF_FF2W1, (size_t)Ln * Dd * DFFd, (int)((size_t)Ln * Dd * DFFd), (int)((size_t)Ln * Dd * DFFd));
        seg(ff2_w2, WR + OFF_FF2W2, (size_t)Ln * DFFd * Dd, (int)((size_t)Ln * DFFd * Dd), (int)((size_t)Ln * DFFd * Dd));
        seg(wo,     WR + OFF_WO,    (size_t)Ln * Dd * Dd, (int)((size_t)Ln * Dd * Dd), (int)((size_t)Ln * Dd * Dd));
        seg(wp,     WR + OFF_WP,    (size_t)Ln * Dd * Dd, (int)((size_t)Ln * Dd * Dd), (int)((size_t)Ln * Dd * Dd));
        seg(pw1_w,  WR + OFF_PW1,   (size_t)Ln * Dd * 2 * Dd, (int)((size_t)Ln * Dd * 2 * Dd), (int)((size_t)Ln * Dd * 2 * Dd));
        seg(pw2_w,  WR + OFF_PW2,   (size_t)Ln * Dd * Dd, (int)((size_t)Ln * Dd * Dd), (int)((size_t)Ln * Dd * Dd));
        seg(pos,    PosR,           (size_t)Pn * Dd, (int)((size_t)Pn * Dd), (int)((size_t)Pn * Dd));
        seg(wq, WR + OFF_WQKV + 0,        (size_t)Ln * Dd * Dd, Dd, 3 * Dd);
        seg(wk, WR + OFF_WQKV + Dd,       (size_t)Ln * Dd * Dd, Dd, 3 * Dd);
        seg(wv, WR + OFF_WQKV + 2 * Dd,   (size_t)Ln * Dd * Dd, Dd, 3 * Dd);
        seg(bq, WR + OFF_BQKV + 0,        (size_t)Ln * Dd, Dd, 3 * Dd);
        seg(bk, WR + OFF_BQKV + Dd,       (size_t)Ln * Dd, Dd, 3 * Dd);
        seg(bv, WR + OFF_BQKV + 2 * Dd,   (size_t)Ln * Dd, Dd, 3 * Dd);
        round_multi<<<dim3(((size_t)Ln * Dd * DFFd + 255) / 256, NSEG), 256>>>(p);
    }

    copy_kernel<<<(BTn * Dd) / 256, 256>>>(in_x, X, BTn * Dd);

    // pos projections for BOTH layers, hoisted + batched
    tf32gemm<0, 2><<<dim3(Dd / 64, (Pn + 127) / 128, Ln), 256, GEMM_SMEM>>>(
        PosR, Dd, WR + OFF_WP, Dd, nullptr, nullptr, Pb, Dd, Pn, Dd, Dd);

    for (int l = 0; l < Ln; ++l) {
        const float* lnS = ln_s + (size_t)l * 5 * Dd;
        const float* lnB = ln_b + (size_t)l * 5 * Dd;

        // ---- macaron FFN 1 (half residual) ----
        ln_kernel<true><<<BTn, 128>>>(X, lnS, lnB, Hb);
        launch_tf32(1, Hb, Dd, WR + OFF_FF1W1 + (size_t)l * Dd * DFFd, DFFd,
                    ff1_b1 + (size_t)l * DFFd, nullptr, FF, DFFd, BTn, DFFd, Dd);
        launch_tf32(3, FF, DFFd, WR + OFF_FF1W2 + (size_t)l * DFFd * Dd, Dd,
                    ff1_b2 + (size_t)l * Dd, X, X, Dd, BTn, Dd, DFFd);

        // ---- rel-pos MHSA ----
        ln_kernel<true><<<BTn, 128>>>(X, lnS + Dd, lnB + Dd, Hb);
        launch_tf32(0, Hb, Dd, WR + OFF_WQKV + (size_t)l * Dd * 3 * Dd, 3 * Dd,
                    WR + OFF_BQKV + (size_t)l * 3 * Dd, nullptr, QKV, 3 * Dd, BTn, 3 * Dd, Dd);

        attn_scores<<<dim3(Tn / 32, Tn / 32, Bn * Hn), 256>>>(
            QKV, 3 * Dd, QKV + Dd, 3 * Dd, Pb + (size_t)l * Pn * Dd,
            bias_u + (size_t)l * Hn * DKn, bias_v + (size_t)l * Hn * DKn, Sb);
        softmax_kernel<<<Bn * Hn * Tn / 8, 256>>>(Sb);

        tf32gemm<0, 1><<<dim3(1, Tn / 128, Bn * Hn), 256, GEMM_SMEM>>>(
            Sb, Tn, QKV + 2 * Dd, 3 * Dd, nullptr, nullptr, CTX, Dd, Tn, DKn, Tn);

        launch_tf32(2, CTX, Dd, WR + OFF_WO + (size_t)l * Dd * Dd, Dd,
                    bo + (size_t)l * Dd, X, X, Dd, BTn, Dd, Dd);

        // ---- conv module (fused GLU+dwconv+BN-stats; BN folded into bn_tr) ----
        ln_kernel<true><<<BTn, 128>>>(X, lnS + 2 * Dd, lnB + 2 * Dd, Hb);
        launch_tf32(0, Hb, Dd, WR + OFF_PW1 + (size_t)l * Dd * 2 * Dd, 2 * Dd,
                    pw1_b + (size_t)l * 2 * Dd, nullptr, Y2, 2 * Dd, BTn, 2 * Dd, Dd);
        glu_dwconv<<<dim3(Tn / 128, Dd / 8, Bn), 256>>>(
            Y2, dw_w + (size_t)l * Dd * KWn, dw_b + (size_t)l * Dd, CV2);
        bn_tr<<<dim3(Tn / 32, Dd / 32, Bn), 256>>>(
            CV2, bn_g + (size_t)l * Dd, bn_b + (size_t)l * Dd, Hb);
        launch_tf32(2, Hb, Dd, WR + OFF_PW2 + (size_t)l * Dd * Dd, Dd,
                    pw2_b + (size_t)l * Dd, X, X, Dd, BTn, Dd, Dd);

        // ---- macaron FFN 2 (half residual) ----
        ln_kernel<true><<<BTn, 128>>>(X, lnS + 3 * Dd, lnB + 3 * Dd, Hb);
        launch_tf32(1, Hb, Dd, WR + OFF_FF2W1 + (size_t)l * Dd * DFFd, DFFd,
                    ff2_b1 + (size_t)l * DFFd, nullptr, FF, DFFd, BTn, DFFd, Dd);
        launch_tf32(3, FF, DFFd, WR + OFF_FF2W2 + (size_t)l * DFFd * Dd, Dd,
                    ff2_b2 + (size_t)l * Dd, X, X, Dd, BTn, Dd, DFFd);

        // ---- final per-layer LN (full precision) ----
        float* outp = (l == Ln - 1) ? (float*)d_out : X;
        ln_kernel<false><<<BTn, 128>>>(X, lnS + 4 * Dd, lnB + 4 * Dd, outp);
    }
}

// round 17
// speedup vs baseline: 1.0603x; 1.0116x over previous
#include <cuda_runtime.h>
#include <math.h>

// ---------------- problem constants ----------------
constexpr int Dd   = 512;
constexpr int Hn   = 8;
constexpr int DFFd = 2048;
constexpr int KWn  = 31;
constexpr int Ln   = 2;
constexpr int Bn   = 4;
constexpr int Tn   = 1024;
constexpr int DKn  = 64;
constexpr int Pn   = 2 * Tn - 1;      // 2047
constexpr int BTn  = Bn * Tn;         // 4096
constexpr float EPSf   = 1e-5f;
constexpr float SCALEf = 0.125f;      // 1/sqrt(64)

// rounded-weight scratch layout (floats)
constexpr size_t OFF_FF1W1 = 0;
constexpr size_t OFF_FF1W2 = OFF_FF1W1 + (size_t)Ln * Dd * DFFd;
constexpr size_t OFF_FF2W1 = OFF_FF1W2 + (size_t)Ln * DFFd * Dd;
constexpr size_t OFF_FF2W2 = OFF_FF2W1 + (size_t)Ln * Dd * DFFd;
constexpr size_t OFF_WQKV  = OFF_FF2W2 + (size_t)Ln * DFFd * Dd;   // [Ln][512][1536]
constexpr size_t OFF_WO    = OFF_WQKV + (size_t)Ln * Dd * 3 * Dd;
constexpr size_t OFF_WP    = OFF_WO + (size_t)Ln * Dd * Dd;
constexpr size_t OFF_PW1   = OFF_WP + (size_t)Ln * Dd * Dd;
constexpr size_t OFF_PW2   = OFF_PW1 + (size_t)Ln * Dd * 2 * Dd;
constexpr size_t OFF_BQKV  = OFF_PW2 + (size_t)Ln * Dd * Dd;       // [Ln][1536]
constexpr size_t WR_TOTAL  = OFF_BQKV + (size_t)Ln * 3 * Dd;

// GEMM dynamic smem: 3 stages x (A 128x32 + B 32x64) u32
constexpr int GEMM_STAGE_U32 = 128 * 32 + 32 * 64;     // 6144
constexpr int GEMM_SMEM = 3 * GEMM_STAGE_U32 * 4;      // 73728 B

// ---------------- device scratch (allocation-free) ----------------
__device__ float g_X  [BTn * Dd];
__device__ float g_H  [BTn * Dd];
__device__ float g_FF [BTn * DFFd];
__device__ float g_QKV[(size_t)BTn * 3 * Dd];
__device__ float g_P  [(size_t)Ln * Pn * Dd];   // per-layer pos projections
__device__ float g_PosR[Pn * Dd];               // tf32-rounded pos
__device__ float g_S  [(size_t)Bn * Hn * Tn * Tn];  // 128 MB scores
__device__ float g_M  [Bn * Hn * Tn];           // softmax row max
__device__ float g_I  [Bn * Hn * Tn];           // softmax row 1/sum
__device__ float g_CTX[BTn * Dd];
__device__ float g_Y2 [BTn * 2 * Dd];
__device__ float g_CV2[Bn * Dd * Tn];
__device__ float g_part[32][2][Dd];             // BN partials
__device__ float g_WR [WR_TOTAL];               // tf32-rounded weights

__device__ __forceinline__ float sigf(float x) { return 1.0f / (1.0f + __expf(-x)); }

__device__ __forceinline__ unsigned f2tf32(float x) {
    unsigned u;
    asm("cvt.rna.tf32.f32 %0, %1;" : "=r"(u) : "f"(x));
    return u;
}
__device__ __forceinline__ float rnd_tf32(float x) { return __uint_as_float(f2tf32(x)); }

#define MMA_TF32(c0,c1,c2,c3,a0,a1,a2,a3,b0,b1)                              \
    asm volatile(                                                            \
        "mma.sync.aligned.m16n8k8.row.col.f32.tf32.tf32.f32 "                \
        "{%0,%1,%2,%3},{%4,%5,%6,%7},{%8,%9},{%0,%1,%2,%3};"                 \
        : "+f"(c0), "+f"(c1), "+f"(c2), "+f"(c3)                             \
        : "r"(a0), "r"(a1), "r"(a2), "r"(a3), "r"(b0), "r"(b1))

__device__ __forceinline__ void cpa16(unsigned dst, const void* src, int szbytes) {
    asm volatile("cp.async.cg.shared.global [%0], [%1], 16, %2;"
                 :: "r"(dst), "l"(src), "r"(szbytes));
}

// =======================================================================
// TF32 tensor-core GEMM, cp.async 3-stage pipeline, XOR-swizzled dyn smem.
// MODE: 0 = (+bias, rnd), 1 = silu(+bias, rnd), 2 = res + (.), 3 = res + 0.5*(.)
// BMODE: 0 = plain; 2 = weight batch (pos proj).
// =======================================================================
template <int MODE, int BMODE>
__global__ void __launch_bounds__(256) tf32gemm(
    const float* __restrict__ A, int lda,
    const float* __restrict__ W, int ldw,
    const float* __restrict__ bias,
    const float* __restrict__ res,
    float* __restrict__ C, int ldc,
    int M, int N, int Kd)
{
    extern __shared__ unsigned gsm[];

    if (BMODE == 2) {
        int z = blockIdx.z;                       // layer index
        W += (size_t)z * Dd * ldw;
        C += (size_t)z * Pn * ldc;
    }

    const int bm = blockIdx.y * 128, bn = blockIdx.x * 64;
    const int tid  = threadIdx.x;
    const int warp = tid >> 5, lane = tid & 31;
    const int g = lane >> 2, t = lane & 3;
    const int wm = (warp >> 1) * 32, wn = (warp & 1) * 32;

    unsigned smBase = (unsigned)__cvta_generic_to_shared(gsm);

    auto loadTile = [&](int stage, int k0) {
        unsigned aOff = (unsigned)stage * GEMM_STAGE_U32;
#pragma unroll
        for (int i = 0; i < 4; i++) {
            int lin = i * 256 + tid;
            int row = lin >> 3, ck = lin & 7;
            int pc = ck ^ (row & 7);
            unsigned dst = smBase + (aOff + row * 32 + pc * 4) * 4;
            const float* src = A + (size_t)(bm + row) * lda + k0 + ck * 4;
            cpa16(dst, src, (bm + row < M) ? 16 : 0);
        }
        unsigned bOff = aOff + 4096;
#pragma unroll
        for (int i = 0; i < 2; i++) {
            int lin = i * 256 + tid;
            int kr = lin >> 4, c4 = lin & 15;
            int pc = c4 ^ (2 * (kr & 3));
            unsigned dst = smBase + (bOff + kr * 64 + pc * 4) * 4;
            const float* src = W + (size_t)(k0 + kr) * ldw + bn + c4 * 4;
            cpa16(dst, src, 16);
        }
        asm volatile("cp.async.commit_group;");
    };

    float acc[2][4][4] = {};

    int colB[4];
#pragma unroll
    for (int nt = 0; nt < 4; nt++) {
        int nb = wn + nt * 8 + g;
        colB[nt] = (((nb >> 2) ^ (2 * t)) << 2) | (nb & 3);
    }
    const int rA0 = wm + g, rA1 = wm + 16 + g;

    const int nk = Kd >> 5;
    loadTile(0, 0);
    loadTile(1, 32);

    for (int kb = 0; kb < nk; kb++) {
        if (kb + 2 < nk) {
            asm volatile("cp.async.wait_group 1;");
        } else {
            asm volatile("cp.async.wait_group 0;");
        }
        __syncthreads();

        const unsigned* Ac = gsm + (kb % 3) * GEMM_STAGE_U32;
        const unsigned* Bc = Ac + 4096;
#pragma unroll
        for (int kt = 0; kt < 4; kt++) {
            const int c0 = (((2 * kt) ^ g) << 2) | t;
            const int c1 = (((2 * kt + 1) ^ g) << 2) | t;
            const int kr = kt * 8 + t;
            unsigned a[2][4];
            a[0][0] = Ac[rA0 * 32 + c0];       a[0][1] = Ac[(rA0 + 8) * 32 + c0];
            a[0][2] = Ac[rA0 * 32 + c1];       a[0][3] = Ac[(rA0 + 8) * 32 + c1];
            a[1][0] = Ac[rA1 * 32 + c0];       a[1][1] = Ac[(rA1 + 8) * 32 + c0];
            a[1][2] = Ac[rA1 * 32 + c1];       a[1][3] = Ac[(rA1 + 8) * 32 + c1];
            unsigned b[4][2];
#pragma unroll
            for (int nt = 0; nt < 4; nt++) {
                b[nt][0] = Bc[kr * 64 + colB[nt]];
                b[nt][1] = Bc[(kr + 4) * 64 + colB[nt]];
            }
#pragma unroll
            for (int mt = 0; mt < 2; mt++)
#pragma unroll
                for (int nt = 0; nt < 4; nt++)
                    MMA_TF32(acc[mt][nt][0], acc[mt][nt][1], acc[mt][nt][2], acc[mt][nt][3],
                             a[mt][0], a[mt][1], a[mt][2], a[mt][3],
                             b[nt][0], b[nt][1]);
        }
        if (kb + 2 < nk) loadTile((kb + 2) % 3, (kb + 2) * 32);
    }

#pragma unroll
    for (int mt = 0; mt < 2; mt++) {
        int r0 = bm + wm + mt * 16 + g;
        int r1 = r0 + 8;
#pragma unroll
        for (int nt = 0; nt < 4; nt++) {
            int col = bn + wn + nt * 8 + 2 * t;
#pragma unroll
            for (int half = 0; half < 2; half++) {
                int row = half ? r1 : r0;
                if (row >= M) continue;
                float v0 = acc[mt][nt][half * 2 + 0];
                float v1 = acc[mt][nt][half * 2 + 1];
                if (bias) { v0 += bias[col]; v1 += bias[col + 1]; }
                if (MODE == 1) { v0 = v0 * sigf(v0); v1 = v1 * sigf(v1); }
                if (MODE == 0 || MODE == 1) { v0 = rnd_tf32(v0); v1 = rnd_tf32(v1); }
                if (MODE == 2) {
                    v0 = res[(size_t)row * ldc + col] + v0;
                    v1 = res[(size_t)row * ldc + col + 1] + v1;
                }
                if (MODE == 3) {
                    v0 = res[(size_t)row * ldc + col] + 0.5f * v0;
                    v1 = res[(size_t)row * ldc + col + 1] + 0.5f * v1;
                }
                *(float2*)&C[(size_t)row * ldc + col] = make_float2(v0, v1);
            }
        }
    }
}

// =======================================================================
// AV GEMM with exp-on-load: CTX[z] = softmax(S[z]) @ V[z].
// A-path: LDG float4 prefetch -> exp((x-m))*inv -> cvt.rna.tf32 -> STS
// (2-stage double buffer). B (V): 2-stage cp.async. Values produced are
// bit-identical to the old "softmax writes rnd_tf32, cp.async truncates"
// path. M = Tn (no predication).
// =======================================================================
__global__ void __launch_bounds__(256) tf32gemm_avexp(
    const float* __restrict__ S, const float* __restrict__ Mrow,
    const float* __restrict__ Irow,
    const float* __restrict__ W, int ldw,
    float* __restrict__ C, int ldc)
{
    __shared__ unsigned As[2][128][32];
    __shared__ unsigned Bs[2][32][64];

    const int z = blockIdx.z;                       // z = b*8 + h
    const float* A = S + (size_t)z * Tn * Tn;
    W += (size_t)(z >> 3) * Tn * ldw + (size_t)(z & 7) * DKn;
    C += (size_t)(z >> 3) * Tn * ldc + (size_t)(z & 7) * DKn;

    const int bm = blockIdx.y * 128;
    const int tid  = threadIdx.x;
    const int warp = tid >> 5, lane = tid & 31;
    const int g = lane >> 2, t = lane & 3;
    const int wm = (warp >> 1) * 32, wn = (warp & 1) * 32;

    unsigned bsBase = (unsigned)__cvta_generic_to_shared(&Bs[0][0][0]);

    // per-thread fixed A rows (4 chunks) + their softmax stats
    int arow[4];
    float am[4], ai[4];
    float4 pa[4];
#pragma unroll
    for (int i = 0; i < 4; i++) {
        int lin = i * 256 + tid;
        arow[i] = lin >> 3;
        am[i] = Mrow[z * Tn + bm + arow[i]];
        ai[i] = Irow[z * Tn + bm + arow[i]];
    }

    auto loadAregs = [&](int k0) {
#pragma unroll
        for (int i = 0; i < 4; i++) {
            int lin = i * 256 + tid;
            int ck = lin & 7;
            pa[i] = *(const float4*)&A[(size_t)(bm + arow[i]) * Tn + k0 + ck * 4];
        }
    };
    auto stsA = [&](int stage) {
#pragma unroll
        for (int i = 0; i < 4; i++) {
            int lin = i * 256 + tid;
            int ck = lin & 7;
            int pc = ck ^ (arow[i] & 7);
            uint4 u;
            u.x = f2tf32(__expf(pa[i].x - am[i]) * ai[i]);
            u.y = f2tf32(__expf(pa[i].y - am[i]) * ai[i]);
            u.z = f2tf32(__expf(pa[i].z - am[i]) * ai[i]);
            u.w = f2tf32(__expf(pa[i].w - am[i]) * ai[i]);
            *(uint4*)&As[stage][arow[i]][pc * 4] = u;
        }
    };
    auto loadB = [&](int stage, int k0) {
#pragma unroll
        for (int i = 0; i < 2; i++) {
            int lin = i * 256 + tid;
            int kr = lin >> 4, c4 = lin & 15;
            int pc = c4 ^ (2 * (kr & 3));
            unsigned dst = bsBase + (((stage << 5) + kr) * 64 + pc * 4) * 4;
            cpa16(dst, W + (size_t)(k0 + kr) * ldw + c4 * 4, 16);
        }
        asm volatile("cp.async.commit_group;");
    };

    float acc[2][4][4] = {};
    int colB[4];
#pragma unroll
    for (int nt = 0; nt < 4; nt++) {
        int nb = wn + nt * 8 + g;
        colB[nt] = (((nb >> 2) ^ (2 * t)) << 2) | (nb & 3);
    }
    const int rA0 = wm + g, rA1 = wm + 16 + g;

    const int nk = Tn >> 5;         // 32
    loadAregs(0);
    stsA(0);
    loadB(0, 0);

    for (int kb = 0; kb < nk; kb++) {
        const int cur = kb & 1;
        if (kb + 1 < nk) {
            loadB(cur ^ 1, (kb + 1) * 32);
            loadAregs((kb + 1) * 32);
            asm volatile("cp.async.wait_group 1;");
        } else {
            asm volatile("cp.async.wait_group 0;");
        }
        __syncthreads();

#pragma unroll
        for (int kt = 0; kt < 4; kt++) {
            const int c0 = (((2 * kt) ^ g) << 2) | t;
            const int c1 = (((2 * kt + 1) ^ g) << 2) | t;
            const int kr = kt * 8 + t;
            unsigned a[2][4];
            a[0][0] = As[cur][rA0][c0];       a[0][1] = As[cur][rA0 + 8][c0];
            a[0][2] = As[cur][rA0][c1];       a[0][3] = As[cur][rA0 + 8][c1];
            a[1][0] = As[cur][rA1][c0];       a[1][1] = As[cur][rA1 + 8][c0];
            a[1][2] = As[cur][rA1][c1];       a[1][3] = As[cur][rA1 + 8][c1];
            unsigned b[4][2];
#pragma unroll
            for (int nt = 0; nt < 4; nt++) {
                b[nt][0] = Bs[cur][kr][colB[nt]];
                b[nt][1] = Bs[cur][kr + 4][colB[nt]];
            }
#pragma unroll
            for (int mt = 0; mt < 2; mt++)
#pragma unroll
                for (int nt = 0; nt < 4; nt++)
                    MMA_TF32(acc[mt][nt][0], acc[mt][nt][1], acc[mt][nt][2], acc[mt][nt][3],
                             a[mt][0], a[mt][1], a[mt][2], a[mt][3],
                             b[nt][0], b[nt][1]);
        }
        __syncthreads();
        if (kb + 1 < nk) stsA(cur ^ 1);
    }

#pragma unroll
    for (int mt = 0; mt < 2; mt++) {
        int r0 = bm + wm + mt * 16 + g;
        int r1 = r0 + 8;
#pragma unroll
        for (int nt = 0; nt < 4; nt++) {
            int col = wn + nt * 8 + 2 * t;
#pragma unroll
            for (int half = 0; half < 2; half++) {
                int row = half ? r1 : r0;
                float v0 = acc[mt][nt][half * 2 + 0];
                float v1 = acc[mt][nt][half * 2 + 1];
                *(float2*)&C[(size_t)row * ldc + col] = make_float2(v0, v1);
            }
        }
    }
}

// ---------------- LayerNorm: 128 threads, float4, warp shuffles ----------------
template <bool RND>
__global__ void __launch_bounds__(128) ln_kernel(
    const float* __restrict__ x, const float* __restrict__ s,
    const float* __restrict__ b, float* __restrict__ out)
{
    __shared__ float red[8];
    const int row = blockIdx.x;
    const int tid = threadIdx.x;
    const int lane = tid & 31, wid = tid >> 5;
    float4 v = ((const float4*)(x + (size_t)row * Dd))[tid];

    float s1 = v.x + v.y + v.z + v.w;
#pragma unroll
    for (int o = 16; o > 0; o >>= 1) s1 += __shfl_xor_sync(0xffffffffu, s1, o);
    if (lane == 0) red[wid] = s1;
    __syncthreads();
    float mean = (red[0] + red[1] + red[2] + red[3]) * (1.0f / Dd);

    float4 d;
    d.x = v.x - mean; d.y = v.y - mean; d.z = v.z - mean; d.w = v.w - mean;
    float s2 = d.x * d.x + d.y * d.y + d.z * d.z + d.w * d.w;
#pragma unroll
    for (int o = 16; o > 0; o >>= 1) s2 += __shfl_xor_sync(0xffffffffu, s2, o);
    if (lane == 0) red[4 + wid] = s2;
    __syncthreads();
    float rstd = rsqrtf((red[4] + red[5] + red[6] + red[7]) * (1.0f / Dd) + EPSf);

    float4 sc = ((const float4*)s)[tid];
    float4 bc = ((const float4*)b)[tid];
    float4 o4;
    o4.x = d.x * rstd * sc.x + bc.x;
    o4.y = d.y * rstd * sc.y + bc.y;
    o4.z = d.z * rstd * sc.z + bc.z;
    o4.w = d.w * rstd * sc.w + bc.w;
    if (RND) {
        o4.x = rnd_tf32(o4.x); o4.y = rnd_tf32(o4.y);
        o4.z = rnd_tf32(o4.z); o4.w = rnd_tf32(o4.w);
    }
    ((float4*)(out + (size_t)row * Dd))[tid] = o4;
}

// =======================================================================
// rel-pos attention scores on tensor cores (R8-verified).
// =======================================================================
__global__ void __launch_bounds__(256) attn_scores(
    const float* __restrict__ Q, int ldq,
    const float* __restrict__ Km, int ldk,
    const float* __restrict__ Pm,
    const float* __restrict__ bu, const float* __restrict__ bvv,
    float* __restrict__ S)
{
    __shared__ unsigned qs[32][66], kt[32][66], pw[64][66];
    __shared__ float C1[32][33];
    __shared__ float C2[32][68];
    __shared__ float uk[32], vp[64];
    __shared__ float us[64], vs[64];

    const int z = blockIdx.z;
    const int b = z >> 3, h = z & 7;
    const int t0 = blockIdx.y << 5, s0 = blockIdx.x << 5;
    const int tid = threadIdx.x;

    if (tid < 16)
        ((float4*)us)[tid] = ((const float4*)(bu + h * 64))[tid];
    else if (tid < 32)
        ((float4*)vs)[tid - 16] = ((const float4*)(bvv + h * 64))[tid - 16];

    for (int i = tid; i < 512; i += 256) {
        int r = i >> 4, c = (i & 15) * 4;
        float4 q4 = *(const float4*)&Q[(size_t)(b * Tn + t0 + r) * ldq + h * 64 + c];
        qs[r][c + 0] = f2tf32(q4.x);
        qs[r][c + 1] = f2tf32(q4.y);
        qs[r][c + 2] = f2tf32(q4.z);
        qs[r][c + 3] = f2tf32(q4.w);
        float4 k4 = *(const float4*)&Km[(size_t)(b * Tn + s0 + r) * ldk + h * 64 + c];
        kt[r][c + 0] = f2tf32(k4.x);
        kt[r][c + 1] = f2tf32(k4.y);
        kt[r][c + 2] = f2tf32(k4.z);
        kt[r][c + 3] = f2tf32(k4.w);
    }
    const int base = (Tn - 32) - t0 + s0;     // in [0, P-63]
    for (int i = tid; i < 1024; i += 256) {
        int r = i >> 4, c = (i & 15) * 4;
        if (r < 63) {
            float4 p4 = *(const float4*)&Pm[(size_t)(base + r) * Dd + h * 64 + c];
            pw[r][c + 0] = f2tf32(p4.x);
            pw[r][c + 1] = f2tf32(p4.y);
            pw[r][c + 2] = f2tf32(p4.z);
            pw[r][c + 3] = f2tf32(p4.w);
        } else {
            pw[r][c + 0] = 0u; pw[r][c + 1] = 0u; pw[r][c + 2] = 0u; pw[r][c + 3] = 0u;
        }
    }
    __syncthreads();

    const int warp = tid >> 5, lane = tid & 31;
    const int g = lane >> 2, t = lane & 3;
    const int mw  = (warp >> 2) * 16;
    const int nwA = (warp & 3) * 8;
    const int nw2 = (warp & 3) * 16;

    float c1r[4] = {};
    float e[2][4] = {};
#pragma unroll
    for (int k0 = 0; k0 < 64; k0 += 8) {
        const int k = k0 + t;
        unsigned a0 = qs[mw + g][k],     a1 = qs[mw + 8 + g][k];
        unsigned a2 = qs[mw + g][k + 4], a3 = qs[mw + 8 + g][k + 4];
        unsigned b0 = kt[nwA + g][k],    b1 = kt[nwA + g][k + 4];
        MMA_TF32(c1r[0], c1r[1], c1r[2], c1r[3], a0, a1, a2, a3, b0, b1);
#pragma unroll
        for (int nt = 0; nt < 2; nt++) {
            int nb = nw2 + nt * 8 + g;
            unsigned p0 = pw[nb][k], p1 = pw[nb][k + 4];
            MMA_TF32(e[nt][0], e[nt][1], e[nt][2], e[nt][3], a0, a1, a2, a3, p0, p1);
        }
    }
    C1[mw + g][nwA + 2 * t]         = c1r[0];
    C1[mw + g][nwA + 2 * t + 1]     = c1r[1];
    C1[mw + 8 + g][nwA + 2 * t]     = c1r[2];
    C1[mw + 8 + g][nwA + 2 * t + 1] = c1r[3];
#pragma unroll
    for (int nt = 0; nt < 2; nt++) {
        int nb = nw2 + nt * 8;
        C2[mw + g][nb + 2 * t]         = e[nt][0];
        C2[mw + g][nb + 2 * t + 1]     = e[nt][1];
        C2[mw + 8 + g][nb + 2 * t]     = e[nt][2];
        C2[mw + 8 + g][nb + 2 * t + 1] = e[nt][3];
    }

    if (tid < 32) {
        float s = 0.f;
#pragma unroll 8
        for (int d = 0; d < 64; d++) s += us[d] * __uint_as_float(kt[tid][d]);
        uk[tid] = s;
    } else if (tid < 96) {
        int r = tid - 32;
        float s = 0.f;
#pragma unroll 8
        for (int d = 0; d < 64; d++) s += vs[d] * __uint_as_float(pw[r][d]);
        vp[r] = s;
    }
    __syncthreads();

    const int tl = tid >> 3, sl = (tid & 7) * 4;
    const int pr = 31 - tl + sl;
    float4 o4;
    o4.x = (C1[tl][sl + 0] + uk[sl + 0] + C2[tl][pr + 0] + vp[pr + 0]) * SCALEf;
    o4.y = (C1[tl][sl + 1] + uk[sl + 1] + C2[tl][pr + 1] + vp[pr + 1]) * SCALEf;
    o4.z = (C1[tl][sl + 2] + uk[sl + 2] + C2[tl][pr + 2] + vp[pr + 2]) * SCALEf;
    o4.w = (C1[tl][sl + 3] + uk[sl + 3] + C2[tl][pr + 3] + vp[pr + 3]) * SCALEf;
    *(float4*)&S[((size_t)z * Tn + (t0 + tl)) * Tn + (s0 + sl)] = o4;
}

// ---------------- softmax stats: warp-per-row, writes m and 1/sum only ----------------
__global__ void __launch_bounds__(256) softmax_stats(
    const float* __restrict__ S, float* __restrict__ Mrow, float* __restrict__ Irow)
{
    const int tid  = threadIdx.x;
    const int warp = tid >> 5, lane = tid & 31;
    const size_t row = (size_t)blockIdx.x * 8 + warp;
    const float4* p = (const float4*)(S + row * Tn);

    float4 v[8];
    float m = -INFINITY;
#pragma unroll
    for (int j = 0; j < 8; j++) {
        v[j] = p[j * 32 + lane];
        m = fmaxf(m, fmaxf(fmaxf(v[j].x, v[j].y), fmaxf(v[j].z, v[j].w)));
    }
#pragma unroll
    for (int o = 16; o > 0; o >>= 1) m = fmaxf(m, __shfl_xor_sync(0xffffffffu, m, o));
    float s = 0.f;
#pragma unroll
    for (int j = 0; j < 8; j++) {
        s += __expf(v[j].x - m) + __expf(v[j].y - m)
           + __expf(v[j].z - m) + __expf(v[j].w - m);
    }
#pragma unroll
    for (int o = 16; o > 0; o >>= 1) s += __shfl_xor_sync(0xffffffffu, s, o);
    if (lane == 0) {
        Mrow[row] = m;
        Irow[row] = 1.0f / s;
    }
}

// =======================================================================
// Fused GLU + depthwise conv (K=31, pad 15) + BN partial stats.
// =======================================================================
__global__ void __launch_bounds__(256) glu_dwconv(
    const float* __restrict__ Y2, const float* __restrict__ w,
    const float* __restrict__ bias, float* __restrict__ out)
{
    __shared__ float gl[8][158];
    __shared__ float sw[8][31];
    const int t0 = blockIdx.x * 128;
    const int d0 = blockIdx.y * 8;
    const int b  = blockIdx.z;
    const int tid = threadIdx.x;
    const int warp = tid >> 5, lane = tid & 31;

    for (int i = tid; i < 8 * 31; i += 256)
        sw[i / 31][i % 31] = w[(d0 + i / 31) * KWn + i % 31];

    for (int i = tid; i < 8 * 158; i += 256) {
        int dl = i & 7, tt = i >> 3;
        int t = t0 - 15 + tt;
        float v = 0.f;
        if (t >= 0 && t < Tn) {
            size_t base = (size_t)(b * Tn + t) * (2 * Dd) + d0 + dl;
            float a = Y2[base];
            float gg = Y2[base + Dd];
            v = a * sigf(gg);
        }
        gl[dl][tt] = v;
    }
    __syncthreads();

    const int d = d0 + warp;
    const float bz = bias[d];
    float s1 = 0.f, s2 = 0.f;
    float* op = out + ((size_t)b * Dd + d) * Tn + t0;
#pragma unroll
    for (int it = 0; it < 4; it++) {
        int tl = it * 32 + lane;
        float acc = bz;
#pragma unroll
        for (int k = 0; k < KWn; k++) acc += gl[warp][tl + k] * sw[warp][k];
        op[tl] = acc;
        s1 += acc;
        s2 += acc * acc;
    }
#pragma unroll
    for (int o = 16; o > 0; o >>= 1) {
        s1 += __shfl_xor_sync(0xffffffffu, s1, o);
        s2 += __shfl_xor_sync(0xffffffffu, s2, o);
    }
    if (lane == 0) {
        int p = b * 8 + blockIdx.x;     // 32 partial slots
        g_part[p][0][d] = s1;
        g_part[p][1][d] = s2;
    }
}

// ---------------- BN apply + SiLU + transpose -> (B,T,D), tf32-rounded ----------------
__global__ void __launch_bounds__(256) bn_tr(
    const float* __restrict__ y, const float* __restrict__ g,
    const float* __restrict__ bt, float* __restrict__ out)
{
    __shared__ float tile[32][33];
    __shared__ float mu_s[32], rs_s[32];
    const int b = blockIdx.z;
    const int d0 = blockIdx.y * 32, t0 = blockIdx.x * 32;
    const int tid = threadIdx.x;
    const int rr = tid >> 5, cc = tid & 31;

    if (tid < 32) {
        int d = d0 + tid;
        float s1 = 0.f, s2 = 0.f;
#pragma unroll
        for (int p = 0; p < 32; p++) {
            s1 += g_part[p][0][d];
            s2 += g_part[p][1][d];
        }
        float mu = s1 * (1.0f / (Bn * Tn));
        float var = s2 * (1.0f / (Bn * Tn)) - mu * mu;
        mu_s[tid] = mu;
        rs_s[tid] = rsqrtf(var + EPSf);
    }
    __syncthreads();

#pragma unroll
    for (int i = 0; i < 4; i++) {
        int dl = rr + i * 8;
        int d = d0 + dl;
        float v = y[((size_t)b * Dd + d) * Tn + t0 + cc];
        v = (v - mu_s[dl]) * rs_s[dl] * g[d] + bt[d];
        v = v * sigf(v);
        tile[dl][cc] = rnd_tf32(v);
    }
    __syncthreads();
#pragma unroll
    for (int i = 0; i < 4; i++) {
        int tl = rr + i * 8;
        out[(size_t)(b * Tn + t0 + tl) * Dd + d0 + cc] = tile[cc][tl];
    }
}

// ---------------- copy ----------------
__global__ void __launch_bounds__(256) copy_kernel(const float* __restrict__ in,
                                                   float* __restrict__ out, int n)
{
    int i = blockIdx.x * 256 + threadIdx.x;
    if (i < n) out[i] = in[i];
}

// ---------------- consolidated tf32 rounding / packing prologue ----------------
constexpr int NSEG = 15;
struct RPack {
    const float* src[NSEG];
    float*       dst[NSEG];
    int n[NSEG];
    int cols[NSEG];
    int dstld[NSEG];
};
__global__ void __launch_bounds__(256) round_multi(RPack p)
{
    int sgi = blockIdx.y;
    int i = blockIdx.x * 256 + threadIdx.x;
    if (i >= p.n[sgi]) return;
    int r = i / p.cols[sgi], c = i - r * p.cols[sgi];
    p.dst[sgi][(size_t)r * p.dstld[sgi] + c] = rnd_tf32(p.src[sgi][i]);
}

// ---------------- host-side launch helper ----------------
static void launch_tf32(int mode,
                        const float* A, int lda,
                        const float* W, int ldw,
                        const float* bias, const float* res,
                        float* C, int ldc,
                        int M, int N, int Kd)
{
    dim3 g(N / 64, (M + 127) / 128, 1);
    switch (mode) {
        case 0: tf32gemm<0, 0><<<g, 256, GEMM_SMEM>>>(A, lda, W, ldw, bias, res, C, ldc, M, N, Kd); break;
        case 1: tf32gemm<1, 0><<<g, 256, GEMM_SMEM>>>(A, lda, W, ldw, bias, res, C, ldc, M, N, Kd); break;
        case 2: tf32gemm<2, 0><<<g, 256, GEMM_SMEM>>>(A, lda, W, ldw, bias, res, C, ldc, M, N, Kd); break;
        case 3: tf32gemm<3, 0><<<g, 256, GEMM_SMEM>>>(A, lda, W, ldw, bias, res, C, ldc, M, N, Kd); break;
    }
}

extern "C" void kernel_launch(void* const* d_in, const int* in_sizes, int n_in,
                              void* d_out, int out_size)
{
    const float* in_x   = (const float*)d_in[0];
    const float* pos    = (const float*)d_in[1];
    const float* ln_s   = (const float*)d_in[2];
    const float* ln_b   = (const float*)d_in[3];
    const float* ff1_w1 = (const float*)d_in[4];
    const float* ff1_b1 = (const float*)d_in[5];
    const float* ff1_w2 = (const float*)d_in[6];
    const float* ff1_b2 = (const float*)d_in[7];
    const float* ff2_w1 = (const float*)d_in[8];
    const float* ff2_b1 = (const float*)d_in[9];
    const float* ff2_w2 = (const float*)d_in[10];
    const float* ff2_b2 = (const float*)d_in[11];
    const float* wq     = (const float*)d_in[12];
    const float* bq     = (const float*)d_in[13];
    const float* wk     = (const float*)d_in[14];
    const float* bk     = (const float*)d_in[15];
    const float* wv     = (const float*)d_in[16];
    const float* bv     = (const float*)d_in[17];
    const float* wp     = (const float*)d_in[18];
    const float* wo     = (const float*)d_in[19];
    const float* bo     = (const float*)d_in[20];
    const float* bias_u = (const float*)d_in[21];
    const float* bias_v = (const float*)d_in[22];
    const float* pw1_w  = (const float*)d_in[23];
    const float* pw1_b  = (const float*)d_in[24];
    const float* dw_w   = (const float*)d_in[25];
    const float* dw_b   = (const float*)d_in[26];
    const float* bn_g   = (const float*)d_in[27];
    const float* bn_b   = (const float*)d_in[28];
    const float* pw2_w  = (const float*)d_in[29];
    const float* pw2_b  = (const float*)d_in[30];
    (void)in_sizes; (void)n_in; (void)out_size;

    float *X, *Hb, *FF, *QKV, *Pb, *PosR, *Sb, *Mr, *Ir, *CTX, *Y2, *CV2, *WR;
    cudaGetSymbolAddress((void**)&X,    g_X);
    cudaGetSymbolAddress((void**)&Hb,   g_H);
    cudaGetSymbolAddress((void**)&FF,   g_FF);
    cudaGetSymbolAddress((void**)&QKV,  g_QKV);
    cudaGetSymbolAddress((void**)&Pb,   g_P);
    cudaGetSymbolAddress((void**)&PosR, g_PosR);
    cudaGetSymbolAddress((void**)&Sb,   g_S);
    cudaGetSymbolAddress((void**)&Mr,   g_M);
    cudaGetSymbolAddress((void**)&Ir,   g_I);
    cudaGetSymbolAddress((void**)&CTX,  g_CTX);
    cudaGetSymbolAddress((void**)&Y2,   g_Y2);
    cudaGetSymbolAddress((void**)&CV2,  g_CV2);
    cudaGetSymbolAddress((void**)&WR,   g_WR);

    cudaFuncSetAttribute((const void*)tf32gemm<0, 0>, cudaFuncAttributeMaxDynamicSharedMemorySize, GEMM_SMEM);
    cudaFuncSetAttribute((const void*)tf32gemm<1, 0>, cudaFuncAttributeMaxDynamicSharedMemorySize, GEMM_SMEM);
    cudaFuncSetAttribute((const void*)tf32gemm<2, 0>, cudaFuncAttributeMaxDynamicSharedMemorySize, GEMM_SMEM);
    cudaFuncSetAttribute((const void*)tf32gemm<3, 0>, cudaFuncAttributeMaxDynamicSharedMemorySize, GEMM_SMEM);
    cudaFuncSetAttribute((const void*)tf32gemm<0, 2>, cudaFuncAttributeMaxDynamicSharedMemorySize, GEMM_SMEM);

    // consolidated tf32 rounding + QKV weight/bias interleave
    {
        RPack p;
        int i = 0;
        auto seg = [&](const float* s, float* d, size_t n, int cols, int ld) {
            p.src[i] = s; p.dst[i] = d; p.n[i] = (int)n; p.cols[i] = cols; p.dstld[i] = ld; i++;
        };
        seg(ff1_w1, WR + OFF_FF1W1, (size_t)Ln * Dd * DFFd, (int)((size_t)Ln * Dd * DFFd), (int)((size_t)Ln * Dd * DFFd));
        seg(ff1_w2, WR + OFF_FF1W2, (size_t)Ln * DFFd * Dd, (int)((size_t)Ln * DFFd * Dd), (int)((size_t)Ln * DFFd * Dd));
        seg(ff2_w1, WR + OFF_FF2W1, (size_t)Ln * Dd * DFFd, (int)((size_t)Ln * Dd * DFFd), (int)((size_t)Ln * Dd * DFFd));
        seg(ff2_w2, WR + OFF_FF2W2, (size_t)Ln * DFFd * Dd, (int)((size_t)Ln * DFFd * Dd), (int)((size_t)Ln * DFFd * Dd));
        seg(wo,     WR + OFF_WO,    (size_t)Ln * Dd * Dd, (int)((size_t)Ln * Dd * Dd), (int)((size_t)Ln * Dd * Dd));
        seg(wp,     WR + OFF_WP,    (size_t)Ln * Dd * Dd, (int)((size_t)Ln * Dd * Dd), (int)((size_t)Ln * Dd * Dd));
        seg(pw1_w,  WR + OFF_PW1,   (size_t)Ln * Dd * 2 * Dd, (int)((size_t)Ln * Dd * 2 * Dd), (int)((size_t)Ln * Dd * 2 * Dd));
        seg(pw2_w,  WR + OFF_PW2,   (size_t)Ln * Dd * Dd, (int)((size_t)Ln * Dd * Dd), (int)((size_t)Ln * Dd * Dd));
        seg(pos,    PosR,           (size_t)Pn * Dd, (int)((size_t)Pn * Dd), (int)((size_t)Pn * Dd));
        seg(wq, WR + OFF_WQKV + 0,        (size_t)Ln * Dd * Dd, Dd, 3 * Dd);
        seg(wk, WR + OFF_WQKV + Dd,       (size_t)Ln * Dd * Dd, Dd, 3 * Dd);
        seg(wv, WR + OFF_WQKV + 2 * Dd,   (size_t)Ln * Dd * Dd, Dd, 3 * Dd);
        seg(bq, WR + OFF_BQKV + 0,        (size_t)Ln * Dd, Dd, 3 * Dd);
        seg(bk, WR + OFF_BQKV + Dd,       (size_t)Ln * Dd, Dd, 3 * Dd);
        seg(bv, WR + OFF_BQKV + 2 * Dd,   (size_t)Ln * Dd, Dd, 3 * Dd);
        round_multi<<<dim3(((size_t)Ln * Dd * DFFd + 255) / 256, NSEG), 256>>>(p);
    }

    copy_kernel<<<(BTn * Dd) / 256, 256>>>(in_x, X, BTn * Dd);

    // pos projections for BOTH layers, hoisted + batched
    tf32gemm<0, 2><<<dim3(Dd / 64, (Pn + 127) / 128, Ln), 256, GEMM_SMEM>>>(
        PosR, Dd, WR + OFF_WP, Dd, nullptr, nullptr, Pb, Dd, Pn, Dd, Dd);

    for (int l = 0; l < Ln; ++l) {
        const float* lnS = ln_s + (size_t)l * 5 * Dd;
        const float* lnB = ln_b + (size_t)l * 5 * Dd;

        // ---- macaron FFN 1 (half residual) ----
        ln_kernel<true><<<BTn, 128>>>(X, lnS, lnB, Hb);
        launch_tf32(1, Hb, Dd, WR + OFF_FF1W1 + (size_t)l * Dd * DFFd, DFFd,
                    ff1_b1 + (size_t)l * DFFd, nullptr, FF, DFFd, BTn, DFFd, Dd);
        launch_tf32(3, FF, DFFd, WR + OFF_FF1W2 + (size_t)l * DFFd * Dd, Dd,
                    ff1_b2 + (size_t)l * Dd, X, X, Dd, BTn, Dd, DFFd);

        // ---- rel-pos MHSA ----
        ln_kernel<true><<<BTn, 128>>>(X, lnS + Dd, lnB + Dd, Hb);
        launch_tf32(0, Hb, Dd, WR + OFF_WQKV + (size_t)l * Dd * 3 * Dd, 3 * Dd,
                    WR + OFF_BQKV + (size_t)l * 3 * Dd, nullptr, QKV, 3 * Dd, BTn, 3 * Dd, Dd);

        attn_scores<<<dim3(Tn / 32, Tn / 32, Bn * Hn), 256>>>(
            QKV, 3 * Dd, QKV + Dd, 3 * Dd, Pb + (size_t)l * Pn * Dd,
            bias_u + (size_t)l * Hn * DKn, bias_v + (size_t)l * Hn * DKn, Sb);
        softmax_stats<<<Bn * Hn * Tn / 8, 256>>>(Sb, Mr, Ir);

        tf32gemm_avexp<<<dim3(1, Tn / 128, Bn * Hn), 256>>>(
            Sb, Mr, Ir, QKV + 2 * Dd, 3 * Dd, CTX, Dd);

        launch_tf32(2, CTX, Dd, WR + OFF_WO + (size_t)l * Dd * Dd, Dd,
                    bo + (size_t)l * Dd, X, X, Dd, BTn, Dd, Dd);

        // ---- conv module (fused GLU+dwconv+BN-stats; BN folded into bn_tr) ----
        ln_kernel<true><<<BTn, 128>>>(X, lnS + 2 * Dd, lnB + 2 * Dd, Hb);
        launch_tf32(0, Hb, Dd, WR + OFF_PW1 + (size_t)l * Dd * 2 * Dd, 2 * Dd,
                    pw1_b + (size_t)l * 2 * Dd, nullptr, Y2, 2 * Dd, BTn, 2 * Dd, Dd);
        glu_dwconv<<<dim3(Tn / 128, Dd / 8, Bn), 256>>>(
            Y2, dw_w + (size_t)l * Dd * KWn, dw_b + (size_t)l * Dd, CV2);
        bn_tr<<<dim3(Tn / 32, Dd / 32, Bn), 256>>>(
            CV2, bn_g + (size_t)l * Dd, bn_b + (size_t)l * Dd, Hb);
        launch_tf32(2, Hb, Dd, WR + OFF_PW2 + (size_t)l * Dd * Dd, Dd,
                    pw2_b + (size_t)l * Dd, X, X, Dd, BTn, Dd, Dd);

        // ---- macaron FFN 2 (half residual) ----
        ln_kernel<true><<<BTn, 128>>>(X, lnS + 3 * Dd, lnB + 3 * Dd, Hb);
        launch_tf32(1, Hb, Dd, WR + OFF_FF2W1 + (size_t)l * Dd * DFFd, DFFd,
                    ff2_b1 + (size_t)l * DFFd, nullptr, FF, DFFd, BTn, DFFd, Dd);
        launch_tf32(3, FF, DFFd, WR + OFF_FF2W2 + (size_t)l * DFFd * Dd, Dd,
                    ff2_b2 + (size_t)l * Dd, X, X, Dd, BTn, Dd, DFFd);

        // ---- final per-layer LN (full precision) ----
        float* outp = (l == Ln - 1) ? (float*)d_out : X;
        ln_kernel<false><<<BTn, 128>>>(X, lnS + 4 * Dd, lnB + 4 * Dd, outp);
    }
}